// round 1
// baseline (speedup 1.0000x reference)
#include <cuda_runtime.h>
#include <math.h>

#define SEQ 2048
#define BSZ 2
#define DIM 1024
#define NH 16
#define HDIM 64
#define WIN 8
#define PH 256
#define BH (BSZ*NH)
#define NROWS (SEQ*BSZ)
#define PROWS (PH*BSZ)

// -------- scratch (device globals; no allocation allowed) --------
__device__ float g_phrase[PROWS*DIM];
__device__ float g_qb[BH*SEQ*HDIM];
__device__ float g_kb[BH*SEQ*HDIM];
__device__ float g_v [BH*SEQ*HDIM];
__device__ float g_qg[BH*SEQ*HDIM];
__device__ float g_kg[BH*PH*HDIM];
__device__ float g_gv[BH*PH*HDIM];
__device__ float g_ao[NROWS*DIM];

// -------- phrase max-pooling: phrase[p,b,d] = max_w query[p*W+w,b,d] --------
__global__ __launch_bounds__(256) void maxpool_kernel(const float* __restrict__ q)
{
    int idx = blockIdx.x*256 + threadIdx.x;
    if (idx >= PROWS*DIM) return;
    int d = idx % DIM;
    int r = idx / DIM;          // r = p*BSZ + b
    int b = r % BSZ;
    int p = r / BSZ;
    float m = -1e30f;
    #pragma unroll
    for (int w = 0; w < WIN; w++)
        m = fmaxf(m, q[((size_t)(p*WIN + w)*BSZ + b)*DIM + d]);
    g_phrase[idx] = m;
}

// -------- generic projection GEMM: Y = X @ W^T + bias (optionally scaled),
//          output either row-major (S*B, D) or head layout (B,H,len,HD) --------
template<int HEADOUT>
__global__ __launch_bounds__(256) void gemm_kernel(
    const float* __restrict__ X, const float* __restrict__ W,
    const float* __restrict__ bias, float* __restrict__ out,
    int lenSeq, float scale)
{
    __shared__ float Xs[64][17];
    __shared__ float Ws[64][17];
    int t  = threadIdx.x;
    int tx = t & 15, ty = t >> 4;
    int m0 = blockIdx.y*64, n0 = blockIdx.x*64;
    float acc[4][4] = {};

    int lm = t >> 2;            // load row within tile
    int lk = (t & 3)*4;         // load k-quad

    for (int k0 = 0; k0 < DIM; k0 += 16) {
        float4 xv = *(const float4*)(X + (size_t)(m0+lm)*DIM + k0 + lk);
        float4 wv = *(const float4*)(W + (size_t)(n0+lm)*DIM + k0 + lk);
        Xs[lm][lk+0]=xv.x; Xs[lm][lk+1]=xv.y; Xs[lm][lk+2]=xv.z; Xs[lm][lk+3]=xv.w;
        Ws[lm][lk+0]=wv.x; Ws[lm][lk+1]=wv.y; Ws[lm][lk+2]=wv.z; Ws[lm][lk+3]=wv.w;
        __syncthreads();
        #pragma unroll
        for (int kk = 0; kk < 16; kk++) {
            float a[4], b[4];
            #pragma unroll
            for (int i = 0; i < 4; i++) a[i] = Xs[ty*4+i][kk];
            #pragma unroll
            for (int j = 0; j < 4; j++) b[j] = Ws[tx*4+j][kk];
            #pragma unroll
            for (int i = 0; i < 4; i++)
                #pragma unroll
                for (int j = 0; j < 4; j++)
                    acc[i][j] = fmaf(a[i], b[j], acc[i][j]);
        }
        __syncthreads();
    }

    #pragma unroll
    for (int i = 0; i < 4; i++) {
        int r = m0 + ty*4 + i;
        #pragma unroll
        for (int j = 0; j < 4; j++) {
            int o = n0 + tx*4 + j;
            float val = (acc[i][j] + bias[o]) * scale;
            if (HEADOUT) {
                int s = r / BSZ, b = r % BSZ;
                int h = o >> 6, hd = o & 63;
                out[(((size_t)(b*NH + h)*lenSeq + s) << 6) + hd] = val;
            } else {
                out[(size_t)r*DIM + o] = val;
            }
        }
    }
}

// -------- gv[b,h,p,:] = sum_j gauss(p,j) * v[b,h,j,:]  (gaussian truncated ±32) --------
__global__ __launch_bounds__(64) void gv_kernel()
{
    int p = blockIdx.x, head = blockIdx.y, hd = threadIdx.x;
    float mu = p*WIN + (WIN-1)*0.5f;            // p*8 + 3.5
    int j0 = p*WIN - 28; if (j0 < 0) j0 = 0;
    int j1 = p*WIN + 36; if (j1 > SEQ) j1 = SEQ;
    const float coef = 0.19947114020071635f;    // 1/(sqrt(2*pi)*sigma), sigma=2
    const float* vp = g_v + (size_t)head*SEQ*HDIM;
    float acc = 0.f;
    for (int j = j0; j < j1; j++) {
        float d = (float)j - mu;
        float w = coef * __expf(-d*d*0.125f);   // /(2*sigma^2)=8
        acc = fmaf(w, vp[(size_t)j*HDIM + hd], acc);
    }
    g_gv[((size_t)head*PH + p)*HDIM + hd] = acc;
}

// -------- fused attention helpers --------
__device__ __forceinline__ void compute_scores(
    int t, const float (*Q)[65], const float (*Ks)[65], float (*Ss)[65])
{
    int rb = (t >> 4)*4, cb = (t & 15)*4;
    float acc[4][4] = {};
    #pragma unroll 16
    for (int kk = 0; kk < 64; kk++) {
        float a[4], b[4];
        #pragma unroll
        for (int i = 0; i < 4; i++) a[i] = Q[rb+i][kk];
        #pragma unroll
        for (int j = 0; j < 4; j++) b[j] = Ks[cb+j][kk];
        #pragma unroll
        for (int i = 0; i < 4; i++)
            #pragma unroll
            for (int j = 0; j < 4; j++)
                acc[i][j] = fmaf(a[i], b[j], acc[i][j]);
    }
    #pragma unroll
    for (int i = 0; i < 4; i++)
        #pragma unroll
        for (int j = 0; j < 4; j++)
            Ss[rb+i][cb+j] = acc[i][j];
}

__device__ __forceinline__ void softmax_update(
    int t, float (*Ss)[65], const float (*Vs)[65],
    float& m, float& l, float O[16])
{
    int row = t >> 2, q4 = t & 3;
    float tmax = -1e30f;
    #pragma unroll
    for (int c = 0; c < 16; c++) tmax = fmaxf(tmax, Ss[row][q4*16 + c]);
    tmax = fmaxf(tmax, __shfl_xor_sync(0xffffffffu, tmax, 1));
    tmax = fmaxf(tmax, __shfl_xor_sync(0xffffffffu, tmax, 2));
    float mnew = fmaxf(m, tmax);
    float corr = __expf(m - mnew);
    #pragma unroll
    for (int d = 0; d < 16; d++) O[d] *= corr;
    float psum = 0.f;
    #pragma unroll
    for (int c = 0; c < 16; c++) {
        float pv = __expf(Ss[row][q4*16 + c] - mnew);
        Ss[row][q4*16 + c] = pv;
        psum += pv;
    }
    psum += __shfl_xor_sync(0xffffffffu, psum, 1);
    psum += __shfl_xor_sync(0xffffffffu, psum, 2);
    l = l*corr + psum;
    m = mnew;
    __syncwarp();
    int db = q4*16;
    #pragma unroll 8
    for (int j = 0; j < 64; j++) {
        float pv = Ss[row][j];
        #pragma unroll
        for (int d = 0; d < 16; d++)
            O[d] = fmaf(pv, Vs[j][db + d], O[d]);
    }
}

// -------- fused attention: base (S keys) + gaussian (P phrase keys over gv) --------
__global__ __launch_bounds__(256) void attn_kernel()
{
    extern __shared__ float smbuf[];
    float (*Qb)[65] = (float(*)[65])(smbuf);
    float (*Qg)[65] = (float(*)[65])(smbuf + 64*65);
    float (*Ks)[65] = (float(*)[65])(smbuf + 2*64*65);
    float (*Vs)[65] = (float(*)[65])(smbuf + 3*64*65);
    float (*Ss)[65] = (float(*)[65])(smbuf + 4*64*65);

    int head = blockIdx.y;
    int m0   = blockIdx.x*64;
    int t    = threadIdx.x;

    #pragma unroll
    for (int i = 0; i < 16; i++) {
        int e = t + i*256, r = e >> 6, c = e & 63;
        Qb[r][c] = g_qb[((size_t)head*SEQ + m0 + r)*HDIM + c];
        Qg[r][c] = g_qg[((size_t)head*SEQ + m0 + r)*HDIM + c];
    }

    float Ob[16] = {}, Og[16] = {};
    float mb = -1e30f, lb = 0.f, mg = -1e30f, lg = 0.f;

    // base branch: 32 key tiles of 64
    for (int tile = 0; tile < SEQ/64; tile++) {
        const float* kp = g_kb + ((size_t)head*SEQ + tile*64)*HDIM;
        const float* vp = g_v  + ((size_t)head*SEQ + tile*64)*HDIM;
        __syncthreads();
        #pragma unroll
        for (int i = 0; i < 16; i++) {
            int e = t + i*256, r = e >> 6, c = e & 63;
            Ks[r][c] = kp[(size_t)r*HDIM + c];
            Vs[r][c] = vp[(size_t)r*HDIM + c];
        }
        __syncthreads();
        compute_scores(t, Qb, Ks, Ss);
        __syncwarp();
        softmax_update(t, Ss, Vs, mb, lb, Ob);
    }

    // gaussian branch: 4 phrase tiles of 64 (keys = k_g, values = gv)
    for (int tile = 0; tile < PH/64; tile++) {
        const float* kp = g_kg + ((size_t)head*PH + tile*64)*HDIM;
        const float* vp = g_gv + ((size_t)head*PH + tile*64)*HDIM;
        __syncthreads();
        #pragma unroll
        for (int i = 0; i < 16; i++) {
            int e = t + i*256, r = e >> 6, c = e & 63;
            Ks[r][c] = kp[(size_t)r*HDIM + c];
            Vs[r][c] = vp[(size_t)r*HDIM + c];
        }
        __syncthreads();
        compute_scores(t, Qg, Ks, Ss);
        __syncwarp();
        softmax_update(t, Ss, Vs, mg, lg, Og);
    }

    // combine: 0.5*(base/lb + gauss/lg), write to (S,B,D) layout
    int row = t >> 2, q4 = t & 3;
    int s = m0 + row, b = head / NH, h = head % NH;
    float ib = 0.5f/lb, ig = 0.5f/lg;
    float* op = g_ao + ((size_t)(s*BSZ + b))*DIM + h*HDIM + q4*16;
    #pragma unroll
    for (int d = 0; d < 16; d++) op[d] = Ob[d]*ib + Og[d]*ig;
}

// -------- launch --------
extern "C" void kernel_launch(void* const* d_in, const int* in_sizes, int n_in,
                              void* d_out, int out_size)
{
    const float* query = (const float*)d_in[0];
    const float* Wqb = (const float*)d_in[1];  const float* bqb = (const float*)d_in[2];
    const float* Wkb = (const float*)d_in[3];  const float* bkb = (const float*)d_in[4];
    const float* Wqg = (const float*)d_in[5];  const float* bqg = (const float*)d_in[6];
    const float* Wkg = (const float*)d_in[7];  const float* bkg = (const float*)d_in[8];
    const float* Wv  = (const float*)d_in[9];  const float* bv  = (const float*)d_in[10];
    const float* Wo  = (const float*)d_in[11]; const float* bo  = (const float*)d_in[12];
    float* out = (float*)d_out;

    float *p_phrase, *p_qb, *p_kb, *p_v, *p_qg, *p_kg, *p_ao;
    cudaGetSymbolAddress((void**)&p_phrase, g_phrase);
    cudaGetSymbolAddress((void**)&p_qb, g_qb);
    cudaGetSymbolAddress((void**)&p_kb, g_kb);
    cudaGetSymbolAddress((void**)&p_v,  g_v);
    cudaGetSymbolAddress((void**)&p_qg, g_qg);
    cudaGetSymbolAddress((void**)&p_kg, g_kg);
    cudaGetSymbolAddress((void**)&p_ao, g_ao);

    const float scaling = 0.125f;   // HD^-0.5 = 64^-0.5

    maxpool_kernel<<<(PROWS*DIM + 255)/256, 256>>>(query);

    dim3 gb(DIM/64, NROWS/64);
    gemm_kernel<1><<<gb, 256>>>(query, Wqb, bqb, p_qb, SEQ, scaling);
    gemm_kernel<1><<<gb, 256>>>(query, Wkb, bkb, p_kb, SEQ, 1.f);
    gemm_kernel<1><<<gb, 256>>>(query, Wv,  bv,  p_v,  SEQ, 1.f);
    gemm_kernel<1><<<gb, 256>>>(query, Wqg, bqg, p_qg, SEQ, scaling);

    dim3 gp(DIM/64, PROWS/64);
    gemm_kernel<1><<<gp, 256>>>(p_phrase, Wkg, bkg, p_kg, PH, 1.f);

    gv_kernel<<<dim3(PH, BH), HDIM>>>();

    int smem = 5*64*65*4;   // 83200 B
    cudaFuncSetAttribute(attn_kernel, cudaFuncAttributeMaxDynamicSharedMemorySize, smem);
    attn_kernel<<<dim3(SEQ/64, BH), 256, smem>>>();

    gemm_kernel<0><<<gb, 256>>>(p_ao, Wo, bo, out, SEQ, 1.f);
}

// round 8
// speedup vs baseline: 2.5148x; 2.5148x over previous
#include <cuda_runtime.h>
#include <cstdint>
#include <math.h>

#define SEQ 2048
#define BSZ 2
#define DIM 1024
#define NH 16
#define HDIM 64
#define WIN 8
#define PH 256
#define BH (BSZ*NH)
#define NROWS (SEQ*BSZ)
#define PROWS (PH*BSZ)

// -------- scratch (device globals; no allocation allowed) --------
__device__ float g_phrase[PROWS*DIM];
__device__ float g_qb[BH*SEQ*HDIM];
__device__ float g_kb[BH*SEQ*HDIM];
__device__ float g_v [BH*SEQ*HDIM];
__device__ float g_qg[BH*SEQ*HDIM];
__device__ float g_kg[BH*PH*HDIM];
__device__ float g_gv[BH*PH*HDIM];
__device__ float g_ao[NROWS*DIM];

// ================= helpers =================
__device__ __forceinline__ uint32_t f2tf(float x){
    uint32_t r; asm("cvt.rna.tf32.f32 %0, %1;" : "=r"(r) : "f"(x)); return r;
}
__device__ __forceinline__ void mma_tf32_16n8k8(float* d, const uint32_t* a, const uint32_t* b){
    asm volatile(
        "mma.sync.aligned.m16n8k8.row.col.f32.tf32.tf32.f32 "
        "{%0,%1,%2,%3}, {%4,%5,%6,%7}, {%8,%9}, {%0,%1,%2,%3};"
        : "+f"(d[0]), "+f"(d[1]), "+f"(d[2]), "+f"(d[3])
        : "r"(a[0]), "r"(a[1]), "r"(a[2]), "r"(a[3]), "r"(b[0]), "r"(b[1]));
}

// ================= phrase max-pooling =================
__global__ __launch_bounds__(256) void maxpool_kernel(const float* __restrict__ q)
{
    int idx = blockIdx.x*256 + threadIdx.x;
    if (idx >= PROWS*DIM) return;
    int d = idx % DIM;
    int r = idx / DIM;
    int b = r % BSZ;
    int p = r / DIM * 0 + r / BSZ;   // r = p*BSZ + b
    float m = -1e30f;
    #pragma unroll
    for (int w = 0; w < WIN; w++)
        m = fmaxf(m, q[((size_t)(p*WIN + w)*BSZ + b)*DIM + d]);
    g_phrase[idx] = m;
}

// ================= tf32 mma.sync GEMM: Y = (X @ W^T + bias) * scale =================
// 128x128 CTA tile, 8 warps (2x4 of 64x32 warptiles), K-chunk 32, double-buffered.
#define SST 36          // smem row stride in floats
#define CHF (128*SST)   // floats per stage per matrix

__global__ __launch_bounds__(256) void mm_tc(
    const float* __restrict__ X, const float* __restrict__ W,
    const float* __restrict__ bias, float* __restrict__ out,
    int lenSeq, float scale, int headout)
{
    extern __shared__ float sm[];
    float* Xs = sm;               // 2 stages
    float* Ws = sm + 2*CHF;

    int t = threadIdx.x, lane = t & 31, wid = t >> 5;
    int m0 = blockIdx.y*128, n0 = blockIdx.x*128;
    int m0w = (wid & 1)*64, n0w = (wid >> 1)*32;

    const float* Xp = X + (size_t)m0*DIM;
    const float* Wp = W + (size_t)n0*DIM;

    // stage-load index: 1024 float4s / 256 threads = 4 each
    int lr[4], lc[4];
    #pragma unroll
    for (int i = 0; i < 4; i++){ int idx = t + i*256; lr[i] = idx >> 3; lc[i] = (idx & 7)*4; }

    // preload chunk 0
    #pragma unroll
    for (int i = 0; i < 4; i++){
        float4 xv = *(const float4*)(Xp + (size_t)lr[i]*DIM + lc[i]);
        float4 wv = *(const float4*)(Wp + (size_t)lr[i]*DIM + lc[i]);
        float* xd = Xs + lr[i]*SST + lc[i];
        float* wd = Ws + lr[i]*SST + lc[i];
        xd[0]=__uint_as_float(f2tf(xv.x)); xd[1]=__uint_as_float(f2tf(xv.y));
        xd[2]=__uint_as_float(f2tf(xv.z)); xd[3]=__uint_as_float(f2tf(xv.w));
        wd[0]=__uint_as_float(f2tf(wv.x)); wd[1]=__uint_as_float(f2tf(wv.y));
        wd[2]=__uint_as_float(f2tf(wv.z)); wd[3]=__uint_as_float(f2tf(wv.w));
    }
    __syncthreads();

    float acc[4][4][4] = {};
    float4 px[4], pw[4];

    #pragma unroll 1
    for (int c = 0; c < DIM/32; c++){
        int cur = c & 1;
        if (c < DIM/32 - 1){
            #pragma unroll
            for (int i = 0; i < 4; i++){
                px[i] = *(const float4*)(Xp + (size_t)lr[i]*DIM + (c+1)*32 + lc[i]);
                pw[i] = *(const float4*)(Wp + (size_t)lr[i]*DIM + (c+1)*32 + lc[i]);
            }
        }
        const float* xb = Xs + cur*CHF;
        const float* wb = Ws + cur*CHF;
        #pragma unroll
        for (int ks = 0; ks < 4; ks++){
            uint32_t af[4][4], bf[4][2];
            #pragma unroll
            for (int mt = 0; mt < 4; mt++){
                const float* p = xb + (m0w + mt*16 + (lane>>2))*SST + ks*8 + (lane&3);
                af[mt][0] = __float_as_uint(p[0]);
                af[mt][1] = __float_as_uint(p[8*SST]);
                af[mt][2] = __float_as_uint(p[4]);
                af[mt][3] = __float_as_uint(p[8*SST + 4]);
            }
            #pragma unroll
            for (int nt = 0; nt < 4; nt++){
                const float* p = wb + (n0w + nt*8 + (lane>>2))*SST + ks*8 + (lane&3);
                bf[nt][0] = __float_as_uint(p[0]);
                bf[nt][1] = __float_as_uint(p[4]);
            }
            #pragma unroll
            for (int mt = 0; mt < 4; mt++)
                #pragma unroll
                for (int nt = 0; nt < 4; nt++)
                    mma_tf32_16n8k8(acc[mt][nt], af[mt], bf[nt]);
        }
        if (c < DIM/32 - 1){
            int nxt = cur ^ 1;
            #pragma unroll
            for (int i = 0; i < 4; i++){
                float* xd = Xs + nxt*CHF + lr[i]*SST + lc[i];
                float* wd = Ws + nxt*CHF + lr[i]*SST + lc[i];
                xd[0]=__uint_as_float(f2tf(px[i].x)); xd[1]=__uint_as_float(f2tf(px[i].y));
                xd[2]=__uint_as_float(f2tf(px[i].z)); xd[3]=__uint_as_float(f2tf(px[i].w));
                wd[0]=__uint_as_float(f2tf(pw[i].x)); wd[1]=__uint_as_float(f2tf(pw[i].y));
                wd[2]=__uint_as_float(f2tf(pw[i].z)); wd[3]=__uint_as_float(f2tf(pw[i].w));
            }
        }
        __syncthreads();
    }

    // epilogue
    #pragma unroll
    for (int mt = 0; mt < 4; mt++){
        int r0 = m0 + m0w + mt*16 + (lane>>2);
        #pragma unroll
        for (int half = 0; half < 2; half++){
            int r = r0 + half*8;
            int s = r / BSZ, bb = r % BSZ;
            #pragma unroll
            for (int nt = 0; nt < 4; nt++){
                int cc = n0 + n0w + nt*8 + 2*(lane&3);
                float v0 = (acc[mt][nt][half*2+0] + bias[cc])   * scale;
                float v1 = (acc[mt][nt][half*2+1] + bias[cc+1]) * scale;
                if (headout){
                    int h = cc >> 6, hd = cc & 63;
                    float* op = out + (((size_t)(bb*NH + h)*lenSeq + s) << 6) + hd;
                    op[0] = v0; op[1] = v1;
                } else {
                    float* op = out + (size_t)r*DIM + cc;
                    op[0] = v0; op[1] = v1;
                }
            }
        }
    }
}

// ================= gv[b,h,p,:] = sum_j gauss(p,j)*v[b,h,j,:] (truncated ±32) =================
__global__ __launch_bounds__(64) void gv_kernel()
{
    int p = blockIdx.x, head = blockIdx.y, hd = threadIdx.x;
    float mu = p*WIN + (WIN-1)*0.5f;
    int j0 = p*WIN - 28; if (j0 < 0) j0 = 0;
    int j1 = p*WIN + 36; if (j1 > SEQ) j1 = SEQ;
    const float coef = 0.19947114020071635f;
    const float* vp = g_v + (size_t)head*SEQ*HDIM;
    float acc = 0.f;
    for (int j = j0; j < j1; j++) {
        float d = (float)j - mu;
        float w = coef * __expf(-d*d*0.125f);
        acc = fmaf(w, vp[(size_t)j*HDIM + hd], acc);
    }
    g_gv[((size_t)head*PH + p)*HDIM + hd] = acc;
}

// ================= fused attention (SIMT 8x4 microtiles, K transposed in smem) =================
#define PAD 68

__device__ __forceinline__ void microtile_fma(
    float (&O)[8][4], const float* __restrict__ Arow, const float* __restrict__ Bk,
    int rb, int cb)
{
    // O[i][j] += sum_k Arow[(rb+i)*PAD + k] * Bk[k*PAD + cb + j],  k = 0..63
    #pragma unroll 4
    for (int kq = 0; kq < 16; kq++){
        float4 b0 = *(const float4*)(Bk + (kq*4+0)*PAD + cb);
        float4 b1 = *(const float4*)(Bk + (kq*4+1)*PAD + cb);
        float4 b2 = *(const float4*)(Bk + (kq*4+2)*PAD + cb);
        float4 b3 = *(const float4*)(Bk + (kq*4+3)*PAD + cb);
        #pragma unroll
        for (int i = 0; i < 8; i++){
            float4 a4 = *(const float4*)(Arow + (rb+i)*PAD + kq*4);
            O[i][0] = fmaf(a4.x, b0.x, O[i][0]); O[i][1] = fmaf(a4.x, b0.y, O[i][1]);
            O[i][2] = fmaf(a4.x, b0.z, O[i][2]); O[i][3] = fmaf(a4.x, b0.w, O[i][3]);
            O[i][0] = fmaf(a4.y, b1.x, O[i][0]); O[i][1] = fmaf(a4.y, b1.y, O[i][1]);
            O[i][2] = fmaf(a4.y, b1.z, O[i][2]); O[i][3] = fmaf(a4.y, b1.w, O[i][3]);
            O[i][0] = fmaf(a4.z, b2.x, O[i][0]); O[i][1] = fmaf(a4.z, b2.y, O[i][1]);
            O[i][2] = fmaf(a4.z, b2.z, O[i][2]); O[i][3] = fmaf(a4.z, b2.w, O[i][3]);
            O[i][0] = fmaf(a4.w, b3.x, O[i][0]); O[i][1] = fmaf(a4.w, b3.y, O[i][1]);
            O[i][2] = fmaf(a4.w, b3.z, O[i][2]); O[i][3] = fmaf(a4.w, b3.w, O[i][3]);
        }
    }
}

__device__ __forceinline__ void attn_branch(
    const float* __restrict__ Q, const float* __restrict__ Kbase, const float* __restrict__ Vbase,
    int ntiles, float (&O)[8][4],
    float* __restrict__ KT, float* __restrict__ Vs, float* __restrict__ Ss,
    float* __restrict__ s_m, float* __restrict__ s_l, float* __restrict__ s_c,
    int t, int tx, int ty)
{
    int rb = ty*8, cb = tx*4;
    for (int tile = 0; tile < ntiles; tile++){
        __syncthreads();
        const float* kp = Kbase + (size_t)tile*64*HDIM;
        const float* vp = Vbase + (size_t)tile*64*HDIM;
        #pragma unroll
        for (int i = 0; i < 8; i++){
            int idx = t + i*128;                 // 1024 float4s
            int r = idx >> 4, c4 = (idx & 15)*4;
            float4 kv = *(const float4*)(kp + (size_t)r*HDIM + c4);
            float4 vv = *(const float4*)(vp + (size_t)r*HDIM + c4);
            KT[(c4+0)*PAD + r] = kv.x;           // transposed: KT[hd][key]
            KT[(c4+1)*PAD + r] = kv.y;
            KT[(c4+2)*PAD + r] = kv.z;
            KT[(c4+3)*PAD + r] = kv.w;
            *(float4*)(Vs + r*PAD + c4) = vv;    // row-major: Vs[key][hd]
        }
        __syncthreads();

        // ---- scores: S[row][col] = sum_hd Q[row][hd] * KT[hd][col] ----
        float acc[8][4] = {};
        microtile_fma(acc, Q, KT, rb, cb);
        #pragma unroll
        for (int i = 0; i < 8; i++)
            #pragma unroll
            for (int j = 0; j < 4; j++)
                Ss[(rb+i)*PAD + cb + j] = acc[i][j];
        __syncthreads();

        // ---- online softmax: 2 threads per row ----
        {
            int row = t >> 1, hf = t & 1;
            float* srow = Ss + row*PAD + hf*32;
            float tmax = -1e30f;
            #pragma unroll
            for (int c2 = 0; c2 < 32; c2++) tmax = fmaxf(tmax, srow[c2]);
            tmax = fmaxf(tmax, __shfl_xor_sync(0xffffffffu, tmax, 1));
            float mold = s_m[row];
            float mnew = fmaxf(mold, tmax);
            float ps = 0.f;
            #pragma unroll
            for (int c2 = 0; c2 < 32; c2++){
                float pv = __expf(srow[c2] - mnew);
                srow[c2] = pv; ps += pv;
            }
            ps += __shfl_xor_sync(0xffffffffu, ps, 1);
            if (hf == 0){
                float corr = __expf(mold - mnew);
                s_c[row] = corr;
                s_m[row] = mnew;
                s_l[row] = s_l[row]*corr + ps;
            }
        }
        __syncthreads();

        // ---- PV: O[row][d] = sum_j P[row][j] * Vs[j][d] ----
        #pragma unroll
        for (int i = 0; i < 8; i++){
            float corr = s_c[rb+i];
            #pragma unroll
            for (int j = 0; j < 4; j++) O[i][j] *= corr;
        }
        microtile_fma(O, Ss, Vs, rb, cb);
    }
}

__global__ __launch_bounds__(128) void attn_kernel()
{
    extern __shared__ float smf[];
    float* Qb  = smf;
    float* Qg  = Qb  + 64*PAD;
    float* KT  = Qg  + 64*PAD;
    float* Vs  = KT  + 64*PAD;
    float* Ss  = Vs  + 64*PAD;
    float* s_m = Ss  + 64*PAD;
    float* s_l = s_m + 64;
    float* s_c = s_l + 64;
    float* s_lb= s_c + 64;

    int head = blockIdx.y;
    int m0   = blockIdx.x*64;
    int t    = threadIdx.x;
    int tx   = t & 15, ty = t >> 4;

    const float* qbp = g_qb + ((size_t)head*SEQ + m0)*HDIM;
    const float* qgp = g_qg + ((size_t)head*SEQ + m0)*HDIM;
    #pragma unroll
    for (int i = 0; i < 8; i++){
        int idx = t + i*128;
        int r = idx >> 4, c4 = (idx & 15)*4;
        *(float4*)(Qb + r*PAD + c4) = *(const float4*)(qbp + (size_t)r*HDIM + c4);
        *(float4*)(Qg + r*PAD + c4) = *(const float4*)(qgp + (size_t)r*HDIM + c4);
    }
    if (t < 64){ s_m[t] = -1e30f; s_l[t] = 0.f; }

    float Ob[8][4] = {}, Og[8][4] = {};

    attn_branch(Qb, g_kb + (size_t)head*SEQ*HDIM, g_v  + (size_t)head*SEQ*HDIM,
                SEQ/64, Ob, KT, Vs, Ss, s_m, s_l, s_c, t, tx, ty);
    __syncthreads();
    if (t < 64){ s_lb[t] = s_l[t]; s_m[t] = -1e30f; s_l[t] = 0.f; }

    attn_branch(Qg, g_kg + (size_t)head*PH*HDIM, g_gv + (size_t)head*PH*HDIM,
                PH/64, Og, KT, Vs, Ss, s_m, s_l, s_c, t, tx, ty);
    __syncthreads();

    int rb = ty*8;
    int b = head / NH, h = head % NH;
    #pragma unroll
    for (int i = 0; i < 8; i++){
        int s = m0 + rb + i;
        float ib = 0.5f / s_lb[rb+i];
        float ig = 0.5f / s_l[rb+i];
        float4 o;
        o.x = Ob[i][0]*ib + Og[i][0]*ig;
        o.y = Ob[i][1]*ib + Og[i][1]*ig;
        o.z = Ob[i][2]*ib + Og[i][2]*ig;
        o.w = Ob[i][3]*ib + Og[i][3]*ig;
        *(float4*)(g_ao + ((size_t)(s*BSZ + b))*DIM + h*HDIM + tx*4) = o;
    }
}

// ================= launch =================
extern "C" void kernel_launch(void* const* d_in, const int* in_sizes, int n_in,
                              void* d_out, int out_size)
{
    const float* query = (const float*)d_in[0];
    const float* Wqb = (const float*)d_in[1];  const float* bqb = (const float*)d_in[2];
    const float* Wkb = (const float*)d_in[3];  const float* bkb = (const float*)d_in[4];
    const float* Wqg = (const float*)d_in[5];  const float* bqg = (const float*)d_in[6];
    const float* Wkg = (const float*)d_in[7];  const float* bkg = (const float*)d_in[8];
    const float* Wv  = (const float*)d_in[9];  const float* bv  = (const float*)d_in[10];
    const float* Wo  = (const float*)d_in[11]; const float* bo  = (const float*)d_in[12];
    float* out = (float*)d_out;

    float *p_phrase, *p_qb, *p_kb, *p_v, *p_qg, *p_kg, *p_ao;
    cudaGetSymbolAddress((void**)&p_phrase, g_phrase);
    cudaGetSymbolAddress((void**)&p_qb, g_qb);
    cudaGetSymbolAddress((void**)&p_kb, g_kb);
    cudaGetSymbolAddress((void**)&p_v,  g_v);
    cudaGetSymbolAddress((void**)&p_qg, g_qg);
    cudaGetSymbolAddress((void**)&p_kg, g_kg);
    cudaGetSymbolAddress((void**)&p_ao, g_ao);

    const float scaling = 0.125f;
    const int gemm_smem = 4*CHF*4;                    // 73728 B
    const int attn_smem = (5*64*PAD + 4*64)*4;        // 88064 B
    cudaFuncSetAttribute(mm_tc,       cudaFuncAttributeMaxDynamicSharedMemorySize, gemm_smem);
    cudaFuncSetAttribute(attn_kernel, cudaFuncAttributeMaxDynamicSharedMemorySize, attn_smem);

    maxpool_kernel<<<(PROWS*DIM + 255)/256, 256>>>(query);

    dim3 gb(DIM/128, NROWS/128);
    mm_tc<<<gb, 256, gemm_smem>>>(query, Wqb, bqb, p_qb, SEQ, scaling, 1);
    mm_tc<<<gb, 256, gemm_smem>>>(query, Wkb, bkb, p_kb, SEQ, 1.f,     1);
    mm_tc<<<gb, 256, gemm_smem>>>(query, Wv,  bv,  p_v,  SEQ, 1.f,     1);
    mm_tc<<<gb, 256, gemm_smem>>>(query, Wqg, bqg, p_qg, SEQ, scaling, 1);

    dim3 gp(DIM/128, PROWS/128);
    mm_tc<<<gp, 256, gemm_smem>>>(p_phrase, Wkg, bkg, p_kg, PH, 1.f,   1);

    gv_kernel<<<dim3(PH, BH), HDIM>>>();

    attn_kernel<<<dim3(SEQ/64, BH), 128, attn_smem>>>();

    mm_tc<<<gb, 256, gemm_smem>>>(p_ao, Wo, bo, out, SEQ, 1.f, 0);
}

// round 9
// speedup vs baseline: 5.2882x; 2.1028x over previous
#include <cuda_runtime.h>
#include <cstdint>
#include <math.h>

#define SEQ 2048
#define BSZ 2
#define DIM 1024
#define NH 16
#define HDIM 64
#define WIN 8
#define PH 256
#define BH (BSZ*NH)
#define NROWS (SEQ*BSZ)
#define PROWS (PH*BSZ)

// -------- scratch (device globals; no allocation allowed) --------
__device__ float g_phrase[PROWS*DIM];
__device__ float g_qb[BH*SEQ*HDIM];
__device__ float g_kb[BH*SEQ*HDIM];
__device__ float g_v [BH*SEQ*HDIM];
__device__ float g_qg[BH*SEQ*HDIM];
__device__ float g_kg[BH*PH*HDIM];
__device__ float g_gv[BH*PH*HDIM];
__device__ float g_ao[NROWS*DIM];

// ================= helpers =================
__device__ __forceinline__ uint32_t f2tf(float x){
    uint32_t r; asm("cvt.rna.tf32.f32 %0, %1;" : "=r"(r) : "f"(x)); return r;
}
__device__ __forceinline__ float tf(float x){ return __uint_as_float(f2tf(x)); }
__device__ __forceinline__ void mma_tf32_16n8k8(float* d, const uint32_t* a, const uint32_t* b){
    asm volatile(
        "mma.sync.aligned.m16n8k8.row.col.f32.tf32.tf32.f32 "
        "{%0,%1,%2,%3}, {%4,%5,%6,%7}, {%8,%9}, {%0,%1,%2,%3};"
        : "+f"(d[0]), "+f"(d[1]), "+f"(d[2]), "+f"(d[3])
        : "r"(a[0]), "r"(a[1]), "r"(a[2]), "r"(a[3]), "r"(b[0]), "r"(b[1]));
}

// ================= phrase max-pooling =================
__global__ __launch_bounds__(256) void maxpool_kernel(const float* __restrict__ q)
{
    int idx = blockIdx.x*256 + threadIdx.x;
    if (idx >= PROWS*DIM) return;
    int d = idx % DIM;
    int r = idx / DIM;
    int b = r % BSZ;
    int p = r / BSZ;
    float m = -1e30f;
    #pragma unroll
    for (int w = 0; w < WIN; w++)
        m = fmaxf(m, q[((size_t)(p*WIN + w)*BSZ + b)*DIM + d]);
    g_phrase[idx] = m;
}

// ================= tf32 mma.sync GEMM: Y = (X @ W^T + bias) * scale =================
#define SST 36
#define CHF (128*SST)

__global__ __launch_bounds__(256) void mm_tc(
    const float* __restrict__ X, const float* __restrict__ W,
    const float* __restrict__ bias, float* __restrict__ out,
    int lenSeq, float scale, int headout)
{
    extern __shared__ float sm[];
    float* Xs = sm;
    float* Ws = sm + 2*CHF;

    int t = threadIdx.x, lane = t & 31, wid = t >> 5;
    int m0 = blockIdx.y*128, n0 = blockIdx.x*128;
    int m0w = (wid & 1)*64, n0w = (wid >> 1)*32;

    const float* Xp = X + (size_t)m0*DIM;
    const float* Wp = W + (size_t)n0*DIM;

    int lr[4], lc[4];
    #pragma unroll
    for (int i = 0; i < 4; i++){ int idx = t + i*256; lr[i] = idx >> 3; lc[i] = (idx & 7)*4; }

    #pragma unroll
    for (int i = 0; i < 4; i++){
        float4 xv = *(const float4*)(Xp + (size_t)lr[i]*DIM + lc[i]);
        float4 wv = *(const float4*)(Wp + (size_t)lr[i]*DIM + lc[i]);
        float* xd = Xs + lr[i]*SST + lc[i];
        float* wd = Ws + lr[i]*SST + lc[i];
        xd[0]=tf(xv.x); xd[1]=tf(xv.y); xd[2]=tf(xv.z); xd[3]=tf(xv.w);
        wd[0]=tf(wv.x); wd[1]=tf(wv.y); wd[2]=tf(wv.z); wd[3]=tf(wv.w);
    }
    __syncthreads();

    float acc[4][4][4] = {};
    float4 px[4], pw[4];

    #pragma unroll 1
    for (int c = 0; c < DIM/32; c++){
        int cur = c & 1;
        if (c < DIM/32 - 1){
            #pragma unroll
            for (int i = 0; i < 4; i++){
                px[i] = *(const float4*)(Xp + (size_t)lr[i]*DIM + (c+1)*32 + lc[i]);
                pw[i] = *(const float4*)(Wp + (size_t)lr[i]*DIM + (c+1)*32 + lc[i]);
            }
        }
        const float* xb = Xs + cur*CHF;
        const float* wb = Ws + cur*CHF;
        #pragma unroll
        for (int ks = 0; ks < 4; ks++){
            uint32_t af[4][4], bf[4][2];
            #pragma unroll
            for (int mt = 0; mt < 4; mt++){
                const float* p = xb + (m0w + mt*16 + (lane>>2))*SST + ks*8 + (lane&3);
                af[mt][0] = __float_as_uint(p[0]);
                af[mt][1] = __float_as_uint(p[8*SST]);
                af[mt][2] = __float_as_uint(p[4]);
                af[mt][3] = __float_as_uint(p[8*SST + 4]);
            }
            #pragma unroll
            for (int nt = 0; nt < 4; nt++){
                const float* p = wb + (n0w + nt*8 + (lane>>2))*SST + ks*8 + (lane&3);
                bf[nt][0] = __float_as_uint(p[0]);
                bf[nt][1] = __float_as_uint(p[4]);
            }
            #pragma unroll
            for (int mt = 0; mt < 4; mt++)
                #pragma unroll
                for (int nt = 0; nt < 4; nt++)
                    mma_tf32_16n8k8(acc[mt][nt], af[mt], bf[nt]);
        }
        if (c < DIM/32 - 1){
            int nxt = cur ^ 1;
            #pragma unroll
            for (int i = 0; i < 4; i++){
                float* xd = Xs + nxt*CHF + lr[i]*SST + lc[i];
                float* wd = Ws + nxt*CHF + lr[i]*SST + lc[i];
                xd[0]=tf(px[i].x); xd[1]=tf(px[i].y); xd[2]=tf(px[i].z); xd[3]=tf(px[i].w);
                wd[0]=tf(pw[i].x); wd[1]=tf(pw[i].y); wd[2]=tf(pw[i].z); wd[3]=tf(pw[i].w);
            }
        }
        __syncthreads();
    }

    #pragma unroll
    for (int mt = 0; mt < 4; mt++){
        int r0 = m0 + m0w + mt*16 + (lane>>2);
        #pragma unroll
        for (int half = 0; half < 2; half++){
            int r = r0 + half*8;
            int s = r / BSZ, bb = r % BSZ;
            #pragma unroll
            for (int nt = 0; nt < 4; nt++){
                int cc = n0 + n0w + nt*8 + 2*(lane&3);
                float v0 = (acc[mt][nt][half*2+0] + bias[cc])   * scale;
                float v1 = (acc[mt][nt][half*2+1] + bias[cc+1]) * scale;
                if (headout){
                    int h = cc >> 6, hd = cc & 63;
                    float* op = out + (((size_t)(bb*NH + h)*lenSeq + s) << 6) + hd;
                    op[0] = v0; op[1] = v1;
                } else {
                    float* op = out + (size_t)r*DIM + cc;
                    op[0] = v0; op[1] = v1;
                }
            }
        }
    }
}

// ================= gv[b,h,p,:] = sum_j gauss(p,j)*v[b,h,j,:] (truncated ±32) =================
__global__ __launch_bounds__(64) void gv_kernel()
{
    int p = blockIdx.x, head = blockIdx.y, hd = threadIdx.x;
    float mu = p*WIN + (WIN-1)*0.5f;
    int j0 = p*WIN - 28; if (j0 < 0) j0 = 0;
    int j1 = p*WIN + 36; if (j1 > SEQ) j1 = SEQ;
    const float coef = 0.19947114020071635f;
    const float* vp = g_v + (size_t)head*SEQ*HDIM;
    float acc = 0.f;
    for (int j = j0; j < j1; j++) {
        float d = (float)j - mu;
        float w = coef * __expf(-d*d*0.125f);
        acc = fmaf(w, vp[(size_t)j*HDIM + hd], acc);
    }
    g_gv[((size_t)head*PH + p)*HDIM + hd] = acc;
}

// ================= tf32 mma flash attention =================
// 64 Q-rows/CTA, 4 warps, warp owns 16 rows. K/P stride 68, V stride 72.
// P stored with column perm sigma(2q+e)=q+4e; V rows stored with same sigma -> cancels.
#define QST 68
#define KST 68
#define VST 72
#define PST 68
#define ATT_SMEM ((64*QST + 64*KST + 64*VST + 4*16*PST)*4)

__device__ __forceinline__ void attn_branch_tc(
    const float* __restrict__ Kb, const float* __restrict__ Vb, int ntiles,
    const uint32_t (&qf)[8][4], float (&O)[8][4], float& l0, float& l1,
    float* __restrict__ Ks, float* __restrict__ Vs, float* __restrict__ Pw, int t)
{
    int lane = t & 31, r = lane >> 2, q = lane & 3;
    float mr0 = -1e30f, mr1 = -1e30f;
    l0 = 0.f; l1 = 0.f;

    #pragma unroll 1
    for (int tile = 0; tile < ntiles; tile++){
        __syncthreads();
        const float* kp = Kb + (size_t)tile*64*HDIM;
        const float* vp = Vb + (size_t)tile*64*HDIM;
        #pragma unroll
        for (int i = 0; i < 8; i++){
            int idx = t + i*128;
            int row = idx >> 4, c4 = (idx & 15)*4;
            float4 kv = *(const float4*)(kp + (size_t)row*HDIM + c4);
            float4 vv = *(const float4*)(vp + (size_t)row*HDIM + c4);
            float* kd = Ks + row*KST + c4;
            kd[0]=tf(kv.x); kd[1]=tf(kv.y); kd[2]=tf(kv.z); kd[3]=tf(kv.w);
            int c = row & 7;
            int prow = (row & ~7) | ((c & 1) << 2) | (c >> 1);   // sigma
            float* vd = Vs + prow*VST + c4;
            vd[0]=tf(vv.x); vd[1]=tf(vv.y); vd[2]=tf(vv.z); vd[3]=tf(vv.w);
        }
        __syncthreads();

        // ---- scores S = Q @ K^T ----
        float s[8][4] = {};
        #pragma unroll
        for (int ks = 0; ks < 8; ks++){
            uint32_t bf[8][2];
            #pragma unroll
            for (int nt = 0; nt < 8; nt++){
                const float* p = Ks + (nt*8 + r)*KST + ks*8 + q;
                bf[nt][0] = __float_as_uint(p[0]);
                bf[nt][1] = __float_as_uint(p[4]);
            }
            #pragma unroll
            for (int nt = 0; nt < 8; nt++)
                mma_tf32_16n8k8(s[nt], qf[ks], bf[nt]);
        }

        // ---- online softmax (rows r, r+8 per thread; quad reduction) ----
        float tm0 = -1e30f, tm1 = -1e30f;
        #pragma unroll
        for (int nt = 0; nt < 8; nt++){
            tm0 = fmaxf(tm0, fmaxf(s[nt][0], s[nt][1]));
            tm1 = fmaxf(tm1, fmaxf(s[nt][2], s[nt][3]));
        }
        tm0 = fmaxf(tm0, __shfl_xor_sync(0xffffffffu, tm0, 1));
        tm0 = fmaxf(tm0, __shfl_xor_sync(0xffffffffu, tm0, 2));
        tm1 = fmaxf(tm1, __shfl_xor_sync(0xffffffffu, tm1, 1));
        tm1 = fmaxf(tm1, __shfl_xor_sync(0xffffffffu, tm1, 2));
        float mn0 = fmaxf(mr0, tm0), mn1 = fmaxf(mr1, tm1);
        float c0 = __expf(mr0 - mn0), c1 = __expf(mr1 - mn1);
        mr0 = mn0; mr1 = mn1;
        float ps0 = 0.f, ps1 = 0.f;
        #pragma unroll
        for (int nt = 0; nt < 8; nt++){
            float p00 = __expf(s[nt][0] - mn0), p01 = __expf(s[nt][1] - mn0);
            float p10 = __expf(s[nt][2] - mn1), p11 = __expf(s[nt][3] - mn1);
            ps0 += p00 + p01; ps1 += p10 + p11;
            // store under sigma: accum col 2q+e -> smem col q+4e
            Pw[r*PST + nt*8 + q]           = tf(p00);
            Pw[r*PST + nt*8 + q + 4]       = tf(p01);
            Pw[(r+8)*PST + nt*8 + q]       = tf(p10);
            Pw[(r+8)*PST + nt*8 + q + 4]   = tf(p11);
        }
        ps0 += __shfl_xor_sync(0xffffffffu, ps0, 1);
        ps0 += __shfl_xor_sync(0xffffffffu, ps0, 2);
        ps1 += __shfl_xor_sync(0xffffffffu, ps1, 1);
        ps1 += __shfl_xor_sync(0xffffffffu, ps1, 2);
        l0 = l0*c0 + ps0; l1 = l1*c1 + ps1;
        #pragma unroll
        for (int nt = 0; nt < 8; nt++){
            O[nt][0] *= c0; O[nt][1] *= c0; O[nt][2] *= c1; O[nt][3] *= c1;
        }
        __syncwarp();

        // ---- PV: O += P @ V ----
        #pragma unroll
        for (int ks = 0; ks < 8; ks++){
            uint32_t af[4];
            const float* pp = Pw + r*PST + ks*8 + q;
            af[0] = __float_as_uint(pp[0]);
            af[1] = __float_as_uint(pp[8*PST]);
            af[2] = __float_as_uint(pp[4]);
            af[3] = __float_as_uint(pp[8*PST + 4]);
            #pragma unroll
            for (int nt = 0; nt < 8; nt++){
                uint32_t bf2[2];
                const float* vv = Vs + (ks*8 + q)*VST + nt*8 + r;
                bf2[0] = __float_as_uint(vv[0]);
                bf2[1] = __float_as_uint(vv[4*VST]);
                mma_tf32_16n8k8(O[nt], af, bf2);
            }
        }
    }
}

__global__ __launch_bounds__(128) void attn_tc()
{
    extern __shared__ float smf[];
    float* Qs = smf;
    float* Ks = Qs + 64*QST;
    float* Vs = Ks + 64*KST;
    float* Ps = Vs + 64*VST;

    int t = threadIdx.x, lane = t & 31, wid = t >> 5;
    int head = blockIdx.y, m0 = blockIdx.x*64;
    int r = lane >> 2, q = lane & 3;
    float* Pw = Ps + wid*16*PST;

    // stage Q_base, load fragments
    const float* qbp = g_qb + ((size_t)head*SEQ + m0)*HDIM;
    #pragma unroll
    for (int i = 0; i < 8; i++){
        int idx = t + i*128;
        int row = idx >> 4, c4 = (idx & 15)*4;
        float4 v = *(const float4*)(qbp + (size_t)row*HDIM + c4);
        float* d = Qs + row*QST + c4;
        d[0]=tf(v.x); d[1]=tf(v.y); d[2]=tf(v.z); d[3]=tf(v.w);
    }
    __syncthreads();
    uint32_t qf[8][4];
    #pragma unroll
    for (int ks = 0; ks < 8; ks++){
        const float* p = Qs + (wid*16 + r)*QST + ks*8 + q;
        qf[ks][0] = __float_as_uint(p[0]);
        qf[ks][1] = __float_as_uint(p[8*QST]);
        qf[ks][2] = __float_as_uint(p[4]);
        qf[ks][3] = __float_as_uint(p[8*QST + 4]);
    }

    float Of[8][4];
    {
        float O[8][4] = {}; float l0, l1;
        attn_branch_tc(g_kb + (size_t)head*SEQ*HDIM, g_v + (size_t)head*SEQ*HDIM,
                       SEQ/64, qf, O, l0, l1, Ks, Vs, Pw, t);
        float i0 = 0.5f/l0, i1 = 0.5f/l1;
        #pragma unroll
        for (int nt = 0; nt < 8; nt++){
            Of[nt][0] = O[nt][0]*i0; Of[nt][1] = O[nt][1]*i0;
            Of[nt][2] = O[nt][2]*i1; Of[nt][3] = O[nt][3]*i1;
        }
    }

    // restage Q_gauss
    __syncthreads();
    const float* qgp = g_qg + ((size_t)head*SEQ + m0)*HDIM;
    #pragma unroll
    for (int i = 0; i < 8; i++){
        int idx = t + i*128;
        int row = idx >> 4, c4 = (idx & 15)*4;
        float4 v = *(const float4*)(qgp + (size_t)row*HDIM + c4);
        float* d = Qs + row*QST + c4;
        d[0]=tf(v.x); d[1]=tf(v.y); d[2]=tf(v.z); d[3]=tf(v.w);
    }
    __syncthreads();
    #pragma unroll
    for (int ks = 0; ks < 8; ks++){
        const float* p = Qs + (wid*16 + r)*QST + ks*8 + q;
        qf[ks][0] = __float_as_uint(p[0]);
        qf[ks][1] = __float_as_uint(p[8*QST]);
        qf[ks][2] = __float_as_uint(p[4]);
        qf[ks][3] = __float_as_uint(p[8*QST + 4]);
    }
    {
        float O[8][4] = {}; float l0, l1;
        attn_branch_tc(g_kg + (size_t)head*PH*HDIM, g_gv + (size_t)head*PH*HDIM,
                       PH/64, qf, O, l0, l1, Ks, Vs, Pw, t);
        float i0 = 0.5f/l0, i1 = 0.5f/l1;
        #pragma unroll
        for (int nt = 0; nt < 8; nt++){
            Of[nt][0] += O[nt][0]*i0; Of[nt][1] += O[nt][1]*i0;
            Of[nt][2] += O[nt][2]*i1; Of[nt][3] += O[nt][3]*i1;
        }
    }

    // write to (S,B,D)
    int b = head / NH, h = head % NH;
    int s0 = m0 + wid*16 + r;
    #pragma unroll
    for (int nt = 0; nt < 8; nt++){
        int d = nt*8 + 2*q;
        float* o0 = g_ao + ((size_t)(s0*BSZ + b))*DIM + h*HDIM + d;
        o0[0] = Of[nt][0]; o0[1] = Of[nt][1];
        float* o1 = g_ao + ((size_t)((s0+8)*BSZ + b))*DIM + h*HDIM + d;
        o1[0] = Of[nt][2]; o1[1] = Of[nt][3];
    }
}

// ================= launch =================
extern "C" void kernel_launch(void* const* d_in, const int* in_sizes, int n_in,
                              void* d_out, int out_size)
{
    const float* query = (const float*)d_in[0];
    const float* Wqb = (const float*)d_in[1];  const float* bqb = (const float*)d_in[2];
    const float* Wkb = (const float*)d_in[3];  const float* bkb = (const float*)d_in[4];
    const float* Wqg = (const float*)d_in[5];  const float* bqg = (const float*)d_in[6];
    const float* Wkg = (const float*)d_in[7];  const float* bkg = (const float*)d_in[8];
    const float* Wv  = (const float*)d_in[9];  const float* bv  = (const float*)d_in[10];
    const float* Wo  = (const float*)d_in[11]; const float* bo  = (const float*)d_in[12];
    float* out = (float*)d_out;

    float *p_phrase, *p_qb, *p_kb, *p_v, *p_qg, *p_kg, *p_ao;
    cudaGetSymbolAddress((void**)&p_phrase, g_phrase);
    cudaGetSymbolAddress((void**)&p_qb, g_qb);
    cudaGetSymbolAddress((void**)&p_kb, g_kb);
    cudaGetSymbolAddress((void**)&p_v,  g_v);
    cudaGetSymbolAddress((void**)&p_qg, g_qg);
    cudaGetSymbolAddress((void**)&p_kg, g_kg);
    cudaGetSymbolAddress((void**)&p_ao, g_ao);

    const float scaling = 0.125f;
    const int gemm_smem = 4*CHF*4;       // 73728 B
    cudaFuncSetAttribute(mm_tc,   cudaFuncAttributeMaxDynamicSharedMemorySize, gemm_smem);
    cudaFuncSetAttribute(attn_tc, cudaFuncAttributeMaxDynamicSharedMemorySize, ATT_SMEM);

    maxpool_kernel<<<(PROWS*DIM + 255)/256, 256>>>(query);

    dim3 gb(DIM/128, NROWS/128);
    mm_tc<<<gb, 256, gemm_smem>>>(query, Wqb, bqb, p_qb, SEQ, scaling, 1);
    mm_tc<<<gb, 256, gemm_smem>>>(query, Wkb, bkb, p_kb, SEQ, 1.f,     1);
    mm_tc<<<gb, 256, gemm_smem>>>(query, Wv,  bv,  p_v,  SEQ, 1.f,     1);
    mm_tc<<<gb, 256, gemm_smem>>>(query, Wqg, bqg, p_qg, SEQ, scaling, 1);

    dim3 gp(DIM/128, PROWS/128);
    mm_tc<<<gp, 256, gemm_smem>>>(p_phrase, Wkg, bkg, p_kg, PH, 1.f,   1);

    gv_kernel<<<dim3(PH, BH), HDIM>>>();

    attn_tc<<<dim3(SEQ/64, BH), 128, ATT_SMEM>>>();

    mm_tc<<<gb, 256, gemm_smem>>>(p_ao, Wo, bo, out, SEQ, 1.f, 0);
}

// round 10
// speedup vs baseline: 6.9592x; 1.3160x over previous
#include <cuda_runtime.h>
#include <cstdint>
#include <math.h>

#define SEQ 2048
#define BSZ 2
#define DIM 1024
#define NH 16
#define HDIM 64
#define WIN 8
#define PH 256
#define BH (BSZ*NH)
#define NROWS (SEQ*BSZ)
#define PROWS (PH*BSZ)

// -------- scratch (device globals; no allocation allowed) --------
__device__ float g_qb[BH*SEQ*HDIM];
__device__ float g_kb[BH*SEQ*HDIM];
__device__ float g_v [BH*SEQ*HDIM];
__device__ float g_qg[BH*SEQ*HDIM];
__device__ float g_kg[BH*PH*HDIM];
__device__ float g_gv[BH*PH*HDIM];
__device__ float g_ao[NROWS*DIM];
// mma-ready swizzled operands
__device__ float g_xsw [NROWS*DIM];
__device__ float g_aosw[NROWS*DIM];
__device__ float g_phsw[PROWS*DIM];
__device__ float g_wsw [6*DIM*DIM];

// ================= helpers =================
__device__ __forceinline__ uint32_t f2tf(float x){
    uint32_t r; asm("cvt.rna.tf32.f32 %0, %1;" : "=r"(r) : "f"(x)); return r;
}
__device__ __forceinline__ float tf(float x){ return __uint_as_float(f2tf(x)); }
__device__ __forceinline__ void mma_tf32_16n8k8(float* d, const uint32_t* a, const uint32_t* b){
    asm volatile(
        "mma.sync.aligned.m16n8k8.row.col.f32.tf32.tf32.f32 "
        "{%0,%1,%2,%3}, {%4,%5,%6,%7}, {%8,%9}, {%0,%1,%2,%3};"
        : "+f"(d[0]), "+f"(d[1]), "+f"(d[2]), "+f"(d[3])
        : "r"(a[0]), "r"(a[1]), "r"(a[2]), "r"(a[3]), "r"(b[0]), "r"(b[1]));
}
__device__ __forceinline__ uint32_t smem_u32(const void* p){
    uint32_t a;
    asm("{ .reg .u64 t; cvta.to.shared.u64 t, %1; cvt.u32.u64 %0, t; }" : "=r"(a) : "l"(p));
    return a;
}
__device__ __forceinline__ void cpa16(uint32_t sm, const void* g){
    asm volatile("cp.async.cg.shared.global [%0], [%1], 16;" :: "r"(sm), "l"(g));
}
__device__ __forceinline__ void cp_commit(){ asm volatile("cp.async.commit_group;"); }
template<int N> __device__ __forceinline__ void cp_wait(){ asm volatile("cp.async.wait_group %0;" :: "n"(N)); }

// ================= operand pre-swizzle =================
// A layout: [mtile16][ktile8][lane32][4], lane=(m&7)*4+(k&3), e={m+8}{k+4}
__global__ __launch_bounds__(256) void conv_A(const float* __restrict__ src,
                                              float* __restrict__ dst, int M)
{
    int idx = blockIdx.x*256 + threadIdx.x;
    int total = (M >> 4)*128*32;
    if (idx >= total) return;
    int lane = idx & 31;
    int kt = (idx >> 5) & 127;
    int mt = idx >> 12;
    int m = mt*16 + (lane >> 2);
    int k = kt*8 + (lane & 3);
    const float* s = src + (size_t)m*DIM + k;
    float4 o;
    o.x = tf(s[0]); o.y = tf(s[8*DIM]); o.z = tf(s[4]); o.w = tf(s[8*DIM + 4]);
    *(float4*)(dst + (size_t)idx*4) = o;
}

// B layout: [ntile8][ktile8][lane32][2], lane=(n&7)*4+(k&3), e={k+4}
__global__ __launch_bounds__(256) void conv_W6(
    const float* __restrict__ w0, const float* __restrict__ w1,
    const float* __restrict__ w2, const float* __restrict__ w3,
    const float* __restrict__ w4, const float* __restrict__ w5,
    float* __restrict__ dst)
{
    int z = blockIdx.y;
    const float* s;
    switch (z){
        case 0: s = w0; break; case 1: s = w1; break; case 2: s = w2; break;
        case 3: s = w3; break; case 4: s = w4; break; default: s = w5; break;
    }
    int idx = blockIdx.x*256 + threadIdx.x;            // < 524288
    int lane = idx & 31;
    int kt = (idx >> 5) & 127;
    int nt = idx >> 12;
    int n = nt*8 + (lane >> 2);
    int k = kt*8 + (lane & 3);
    const float* p = s + (size_t)n*DIM + k;
    float2 o; o.x = tf(p[0]); o.y = tf(p[4]);
    *(float2*)(dst + (size_t)z*DIM*DIM + (size_t)idx*2) = o;
}

// fused phrase max-pool + A-swizzle
__global__ __launch_bounds__(256) void maxpool_swz(const float* __restrict__ q,
                                                   float* __restrict__ dst)
{
    int idx = blockIdx.x*256 + threadIdx.x;
    int total = (PROWS >> 4)*128*32;                   // 131072
    if (idx >= total) return;
    int lane = idx & 31;
    int kt = (idx >> 5) & 127;
    int mt = idx >> 12;
    int m = mt*16 + (lane >> 2);
    int k = kt*8 + (lane & 3);
    float4 o; float* op = (float*)&o;
    #pragma unroll
    for (int e = 0; e < 4; e++){
        int mm = m + 8*(e & 1);
        int kk = k + 4*(e >> 1);
        int p = mm >> 1, b = mm & 1;
        float v = -1e30f;
        #pragma unroll
        for (int w = 0; w < WIN; w++)
            v = fmaxf(v, q[((size_t)((p*WIN + w)*BSZ + b))*DIM + kk]);
        op[e] = tf(v);
    }
    *(float4*)(dst + (size_t)idx*4) = o;
}

// ================= cp.async pipelined tf32 GEMM on swizzled operands =================
#define STAGES 3
#define SM_A 4096
#define SM_B 4096
#define STAGE_F (SM_A + SM_B)
#define GEMM_SMEM (STAGES*STAGE_F*4)    // 98304 B

__device__ __forceinline__ void gemm_body(
    const float* __restrict__ Asw, const float* __restrict__ Bsw,
    const float* __restrict__ bias, float* __restrict__ out,
    float scale, int headout, int lenSeq, float* sm)
{
    int t = threadIdx.x, lane = t & 31, wid = t >> 5;
    int m0 = blockIdx.y*128, n0 = blockIdx.x*128;
    int my0 = blockIdx.y*8,  ny0 = blockIdx.x*16;
    uint32_t smb = smem_u32(sm);

    #define ISSUE(c, s) do { \
        uint32_t sa_ = smb + (uint32_t)((s)*STAGE_F)*4; \
        uint32_t sb_ = sa_ + SM_A*4; \
        _Pragma("unroll") \
        for (int i = 0; i < 4; i++){ \
            int lin = t + i*256; \
            int ab = lin >> 5, aoff = lin & 31; \
            const float* ga = Asw + (((size_t)(my0 + (ab >> 2))*128 + (c)*4 + (ab & 3))*128 + aoff*4); \
            cpa16(sa_ + (uint32_t)lin*16, ga); \
            int bb = lin >> 4, boff = lin & 15; \
            const float* gb = Bsw + (((size_t)(ny0 + (bb >> 2))*128 + (c)*4 + (bb & 3))*64 + boff*4); \
            cpa16(sb_ + (uint32_t)lin*16, gb); \
        } \
        cp_commit(); \
    } while(0)

    ISSUE(0, 0);
    ISSUE(1, 1);

    float acc[4][4][4] = {};
    int mtw0 = (wid & 1)*4, ntw0 = (wid >> 1)*4;

    #pragma unroll 1
    for (int c = 0; c < 32; c++){
        cp_wait<STAGES-2>();
        __syncthreads();
        if (c + 2 < 32){ int s2 = (c + 2) % STAGES; ISSUE(c+2, s2); }
        const float* sa = sm + (c % STAGES)*STAGE_F;
        const float* sbp = sa + SM_A;
        #pragma unroll
        for (int ks = 0; ks < 4; ks++){
            uint32_t af[4][4], bf[4][2];
            #pragma unroll
            for (int mt = 0; mt < 4; mt++){
                float4 v = *(const float4*)(sa + ((mtw0 + mt)*4 + ks)*128 + lane*4);
                af[mt][0]=__float_as_uint(v.x); af[mt][1]=__float_as_uint(v.y);
                af[mt][2]=__float_as_uint(v.z); af[mt][3]=__float_as_uint(v.w);
            }
            #pragma unroll
            for (int nt = 0; nt < 4; nt++){
                float2 v = *(const float2*)(sbp + ((ntw0 + nt)*4 + ks)*64 + lane*2);
                bf[nt][0]=__float_as_uint(v.x); bf[nt][1]=__float_as_uint(v.y);
            }
            #pragma unroll
            for (int mt = 0; mt < 4; mt++)
                #pragma unroll
                for (int nt = 0; nt < 4; nt++)
                    mma_tf32_16n8k8(acc[mt][nt], af[mt], bf[nt]);
        }
    }
    #undef ISSUE

    int r = lane >> 2, q = lane & 3;
    #pragma unroll
    for (int mt = 0; mt < 4; mt++){
        int r0 = m0 + (wid & 1)*64 + mt*16 + r;
        #pragma unroll
        for (int half = 0; half < 2; half++){
            int rr = r0 + half*8;
            int s = rr / BSZ, bb = rr % BSZ;
            #pragma unroll
            for (int nt = 0; nt < 4; nt++){
                int cc = n0 + (wid >> 1)*32 + nt*8 + 2*q;
                float v0 = (acc[mt][nt][half*2+0] + bias[cc])   * scale;
                float v1 = (acc[mt][nt][half*2+1] + bias[cc+1]) * scale;
                if (headout){
                    int h = cc >> 6, hd = cc & 63;
                    float* op = out + (((size_t)(bb*NH + h)*lenSeq + s) << 6) + hd;
                    op[0] = v0; op[1] = v1;
                } else {
                    float* op = out + (size_t)rr*DIM + cc;
                    op[0] = v0; op[1] = v1;
                }
            }
        }
    }
}

// merged projections: z=0..3 -> X-projections, z=4 -> phrase projection (y<4)
__global__ __launch_bounds__(256, 2) void mm_proj(
    const float* __restrict__ xsw, const float* __restrict__ phsw,
    const float* __restrict__ wsw,
    const float* b0, const float* b1, const float* b2, const float* b3, const float* b4,
    float* o0, float* o1, float* o2, float* o3, float* o4)
{
    extern __shared__ float sm[];
    int z = blockIdx.z;
    if (z == 4 && blockIdx.y >= PROWS/128) return;
    const float* A = (z == 4) ? phsw : xsw;
    const float* B; float* O; const float* bias;
    switch (z){
        case 0: bias = b0; O = o0; break;
        case 1: bias = b1; O = o1; break;
        case 2: bias = b2; O = o2; break;
        case 3: bias = b3; O = o3; break;
        default: bias = b4; O = o4; break;
    }
    B = wsw + (size_t)z*DIM*DIM;
    float sc = (z == 0 || z == 3) ? 0.125f : 1.f;
    int lenSeq = (z == 4) ? PH : SEQ;
    gemm_body(A, B, bias, O, sc, 1, lenSeq, sm);
}

__global__ __launch_bounds__(256, 2) void mm_swz(
    const float* __restrict__ Asw, const float* __restrict__ Bsw,
    const float* __restrict__ bias, float* __restrict__ out,
    float scale, int headout, int lenSeq)
{
    extern __shared__ float sm[];
    gemm_body(Asw, Bsw, bias, out, scale, headout, lenSeq, sm);
}

// ================= gv[b,h,p,:] = sum_j gauss(p,j)*v[b,h,j,:] (truncated ±32) =================
__global__ __launch_bounds__(64) void gv_kernel()
{
    int p = blockIdx.x, head = blockIdx.y, hd = threadIdx.x;
    float mu = p*WIN + (WIN-1)*0.5f;
    int j0 = p*WIN - 28; if (j0 < 0) j0 = 0;
    int j1 = p*WIN + 36; if (j1 > SEQ) j1 = SEQ;
    const float coef = 0.19947114020071635f;
    const float* vp = g_v + (size_t)head*SEQ*HDIM;
    float acc = 0.f;
    for (int j = j0; j < j1; j++) {
        float d = (float)j - mu;
        float w = coef * __expf(-d*d*0.125f);
        acc = fmaf(w, vp[(size_t)j*HDIM + hd], acc);
    }
    g_gv[((size_t)head*PH + p)*HDIM + hd] = acc;
}

// ================= tf32 mma flash attention (unchanged from R9) =================
#define QST 68
#define KST 68
#define VST 72
#define PST 68
#define ATT_SMEM ((64*QST + 64*KST + 64*VST + 4*16*PST)*4)

__device__ __forceinline__ void attn_branch_tc(
    const float* __restrict__ Kb, const float* __restrict__ Vb, int ntiles,
    const uint32_t (&qf)[8][4], float (&O)[8][4], float& l0, float& l1,
    float* __restrict__ Ks, float* __restrict__ Vs, float* __restrict__ Pw, int t)
{
    int lane = t & 31, r = lane >> 2, q = lane & 3;
    float mr0 = -1e30f, mr1 = -1e30f;
    l0 = 0.f; l1 = 0.f;

    #pragma unroll 1
    for (int tile = 0; tile < ntiles; tile++){
        __syncthreads();
        const float* kp = Kb + (size_t)tile*64*HDIM;
        const float* vp = Vb + (size_t)tile*64*HDIM;
        #pragma unroll
        for (int i = 0; i < 8; i++){
            int idx = t + i*128;
            int row = idx >> 4, c4 = (idx & 15)*4;
            float4 kv = *(const float4*)(kp + (size_t)row*HDIM + c4);
            float4 vv = *(const float4*)(vp + (size_t)row*HDIM + c4);
            float* kd = Ks + row*KST + c4;
            kd[0]=tf(kv.x); kd[1]=tf(kv.y); kd[2]=tf(kv.z); kd[3]=tf(kv.w);
            int c = row & 7;
            int prow = (row & ~7) | ((c & 1) << 2) | (c >> 1);   // sigma
            float* vd = Vs + prow*VST + c4;
            vd[0]=tf(vv.x); vd[1]=tf(vv.y); vd[2]=tf(vv.z); vd[3]=tf(vv.w);
        }
        __syncthreads();

        float s[8][4] = {};
        #pragma unroll
        for (int ks = 0; ks < 8; ks++){
            uint32_t bf[8][2];
            #pragma unroll
            for (int nt = 0; nt < 8; nt++){
                const float* p = Ks + (nt*8 + r)*KST + ks*8 + q;
                bf[nt][0] = __float_as_uint(p[0]);
                bf[nt][1] = __float_as_uint(p[4]);
            }
            #pragma unroll
            for (int nt = 0; nt < 8; nt++)
                mma_tf32_16n8k8(s[nt], qf[ks], bf[nt]);
        }

        float tm0 = -1e30f, tm1 = -1e30f;
        #pragma unroll
        for (int nt = 0; nt < 8; nt++){
            tm0 = fmaxf(tm0, fmaxf(s[nt][0], s[nt][1]));
            tm1 = fmaxf(tm1, fmaxf(s[nt][2], s[nt][3]));
        }
        tm0 = fmaxf(tm0, __shfl_xor_sync(0xffffffffu, tm0, 1));
        tm0 = fmaxf(tm0, __shfl_xor_sync(0xffffffffu, tm0, 2));
        tm1 = fmaxf(tm1, __shfl_xor_sync(0xffffffffu, tm1, 1));
        tm1 = fmaxf(tm1, __shfl_xor_sync(0xffffffffu, tm1, 2));
        float mn0 = fmaxf(mr0, tm0), mn1 = fmaxf(mr1, tm1);
        float c0 = __expf(mr0 - mn0), c1 = __expf(mr1 - mn1);
        mr0 = mn0; mr1 = mn1;
        float ps0 = 0.f, ps1 = 0.f;
        #pragma unroll
        for (int nt = 0; nt < 8; nt++){
            float p00 = __expf(s[nt][0] - mn0), p01 = __expf(s[nt][1] - mn0);
            float p10 = __expf(s[nt][2] - mn1), p11 = __expf(s[nt][3] - mn1);
            ps0 += p00 + p01; ps1 += p10 + p11;
            Pw[r*PST + nt*8 + q]           = tf(p00);
            Pw[r*PST + nt*8 + q + 4]       = tf(p01);
            Pw[(r+8)*PST + nt*8 + q]       = tf(p10);
            Pw[(r+8)*PST + nt*8 + q + 4]   = tf(p11);
        }
        ps0 += __shfl_xor_sync(0xffffffffu, ps0, 1);
        ps0 += __shfl_xor_sync(0xffffffffu, ps0, 2);
        ps1 += __shfl_xor_sync(0xffffffffu, ps1, 1);
        ps1 += __shfl_xor_sync(0xffffffffu, ps1, 2);
        l0 = l0*c0 + ps0; l1 = l1*c1 + ps1;
        #pragma unroll
        for (int nt = 0; nt < 8; nt++){
            O[nt][0] *= c0; O[nt][1] *= c0; O[nt][2] *= c1; O[nt][3] *= c1;
        }
        __syncwarp();

        #pragma unroll
        for (int ks = 0; ks < 8; ks++){
            uint32_t af[4];
            const float* pp = Pw + r*PST + ks*8 + q;
            af[0] = __float_as_uint(pp[0]);
            af[1] = __float_as_uint(pp[8*PST]);
            af[2] = __float_as_uint(pp[4]);
            af[3] = __float_as_uint(pp[8*PST + 4]);
            #pragma unroll
            for (int nt = 0; nt < 8; nt++){
                uint32_t bf2[2];
                const float* vv = Vs + (ks*8 + q)*VST + nt*8 + r;
                bf2[0] = __float_as_uint(vv[0]);
                bf2[1] = __float_as_uint(vv[4*VST]);
                mma_tf32_16n8k8(O[nt], af, bf2);
            }
        }
    }
}

__global__ __launch_bounds__(128) void attn_tc()
{
    extern __shared__ float smf[];
    float* Qs = smf;
    float* Ks = Qs + 64*QST;
    float* Vs = Ks + 64*KST;
    float* Ps = Vs + 64*VST;

    int t = threadIdx.x, lane = t & 31, wid = t >> 5;
    int head = blockIdx.y, m0 = blockIdx.x*64;
    int r = lane >> 2, q = lane & 3;
    float* Pw = Ps + wid*16*PST;

    const float* qbp = g_qb + ((size_t)head*SEQ + m0)*HDIM;
    #pragma unroll
    for (int i = 0; i < 8; i++){
        int idx = t + i*128;
        int row = idx >> 4, c4 = (idx & 15)*4;
        float4 v = *(const float4*)(qbp + (size_t)row*HDIM + c4);
        float* d = Qs + row*QST + c4;
        d[0]=tf(v.x); d[1]=tf(v.y); d[2]=tf(v.z); d[3]=tf(v.w);
    }
    __syncthreads();
    uint32_t qf[8][4];
    #pragma unroll
    for (int ks = 0; ks < 8; ks++){
        const float* p = Qs + (wid*16 + r)*QST + ks*8 + q;
        qf[ks][0] = __float_as_uint(p[0]);
        qf[ks][1] = __float_as_uint(p[8*QST]);
        qf[ks][2] = __float_as_uint(p[4]);
        qf[ks][3] = __float_as_uint(p[8*QST + 4]);
    }

    float Of[8][4];
    {
        float O[8][4] = {}; float l0, l1;
        attn_branch_tc(g_kb + (size_t)head*SEQ*HDIM, g_v + (size_t)head*SEQ*HDIM,
                       SEQ/64, qf, O, l0, l1, Ks, Vs, Pw, t);
        float i0 = 0.5f/l0, i1 = 0.5f/l1;
        #pragma unroll
        for (int nt = 0; nt < 8; nt++){
            Of[nt][0] = O[nt][0]*i0; Of[nt][1] = O[nt][1]*i0;
            Of[nt][2] = O[nt][2]*i1; Of[nt][3] = O[nt][3]*i1;
        }
    }

    __syncthreads();
    const float* qgp = g_qg + ((size_t)head*SEQ + m0)*HDIM;
    #pragma unroll
    for (int i = 0; i < 8; i++){
        int idx = t + i*128;
        int row = idx >> 4, c4 = (idx & 15)*4;
        float4 v = *(const float4*)(qgp + (size_t)row*HDIM + c4);
        float* d = Qs + row*QST + c4;
        d[0]=tf(v.x); d[1]=tf(v.y); d[2]=tf(v.z); d[3]=tf(v.w);
    }
    __syncthreads();
    #pragma unroll
    for (int ks = 0; ks < 8; ks++){
        const float* p = Qs + (wid*16 + r)*QST + ks*8 + q;
        qf[ks][0] = __float_as_uint(p[0]);
        qf[ks][1] = __float_as_uint(p[8*QST]);
        qf[ks][2] = __float_as_uint(p[4]);
        qf[ks][3] = __float_as_uint(p[8*QST + 4]);
    }
    {
        float O[8][4] = {}; float l0, l1;
        attn_branch_tc(g_kg + (size_t)head*PH*HDIM, g_gv + (size_t)head*PH*HDIM,
                       PH/64, qf, O, l0, l1, Ks, Vs, Pw, t);
        float i0 = 0.5f/l0, i1 = 0.5f/l1;
        #pragma unroll
        for (int nt = 0; nt < 8; nt++){
            Of[nt][0] += O[nt][0]*i0; Of[nt][1] += O[nt][1]*i0;
            Of[nt][2] += O[nt][2]*i1; Of[nt][3] += O[nt][3]*i1;
        }
    }

    int b = head / NH, h = head % NH;
    int s0 = m0 + wid*16 + r;
    #pragma unroll
    for (int nt = 0; nt < 8; nt++){
        int d = nt*8 + 2*q;
        float* o0 = g_ao + ((size_t)(s0*BSZ + b))*DIM + h*HDIM + d;
        o0[0] = Of[nt][0]; o0[1] = Of[nt][1];
        float* o1 = g_ao + ((size_t)((s0+8)*BSZ + b))*DIM + h*HDIM + d;
        o1[0] = Of[nt][2]; o1[1] = Of[nt][3];
    }
}

// ================= launch =================
extern "C" void kernel_launch(void* const* d_in, const int* in_sizes, int n_in,
                              void* d_out, int out_size)
{
    const float* query = (const float*)d_in[0];
    const float* Wqb = (const float*)d_in[1];  const float* bqb = (const float*)d_in[2];
    const float* Wkb = (const float*)d_in[3];  const float* bkb = (const float*)d_in[4];
    const float* Wqg = (const float*)d_in[5];  const float* bqg = (const float*)d_in[6];
    const float* Wkg = (const float*)d_in[7];  const float* bkg = (const float*)d_in[8];
    const float* Wv  = (const float*)d_in[9];  const float* bv  = (const float*)d_in[10];
    const float* Wo  = (const float*)d_in[11]; const float* bo  = (const float*)d_in[12];
    float* out = (float*)d_out;

    float *p_qb, *p_kb, *p_v, *p_qg, *p_kg, *p_ao;
    float *p_xsw, *p_aosw, *p_phsw, *p_wsw;
    cudaGetSymbolAddress((void**)&p_qb, g_qb);
    cudaGetSymbolAddress((void**)&p_kb, g_kb);
    cudaGetSymbolAddress((void**)&p_v,  g_v);
    cudaGetSymbolAddress((void**)&p_qg, g_qg);
    cudaGetSymbolAddress((void**)&p_kg, g_kg);
    cudaGetSymbolAddress((void**)&p_ao, g_ao);
    cudaGetSymbolAddress((void**)&p_xsw,  g_xsw);
    cudaGetSymbolAddress((void**)&p_aosw, g_aosw);
    cudaGetSymbolAddress((void**)&p_phsw, g_phsw);
    cudaGetSymbolAddress((void**)&p_wsw,  g_wsw);

    cudaFuncSetAttribute(mm_proj, cudaFuncAttributeMaxDynamicSharedMemorySize, GEMM_SMEM);
    cudaFuncSetAttribute(mm_swz,  cudaFuncAttributeMaxDynamicSharedMemorySize, GEMM_SMEM);
    cudaFuncSetAttribute(attn_tc, cudaFuncAttributeMaxDynamicSharedMemorySize, ATT_SMEM);

    // operand pre-swizzle (weight order: qb, kb, v, qg, kg, o)
    conv_W6<<<dim3(2048, 6), 256>>>(Wqb, Wkb, Wv, Wqg, Wkg, Wo, p_wsw);
    conv_A<<<4096, 256>>>(query, p_xsw, NROWS);
    maxpool_swz<<<512, 256>>>(query, p_phsw);

    // merged projections (z: 0=qb(.125) 1=kb 2=v 3=qg(.125) 4=kg from phrase)
    mm_proj<<<dim3(DIM/128, NROWS/128, 5), 256, GEMM_SMEM>>>(
        p_xsw, p_phsw, p_wsw,
        bqb, bkb, bv, bqg, bkg,
        p_qb, p_kb, p_v, p_qg, p_kg);

    gv_kernel<<<dim3(PH, BH), HDIM>>>();

    attn_tc<<<dim3(SEQ/64, BH), 128, ATT_SMEM>>>();

    conv_A<<<4096, 256>>>(p_ao, p_aosw, NROWS);
    mm_swz<<<dim3(DIM/128, NROWS/128), 256, GEMM_SMEM>>>(
        p_aosw, p_wsw + (size_t)5*DIM*DIM, bo, out, 1.f, 0, SEQ);
}

// round 14
// speedup vs baseline: 8.0247x; 1.1531x over previous
#include <cuda_runtime.h>
#include <cstdint>
#include <math.h>

#define SEQ 2048
#define BSZ 2
#define DIM 1024
#define NH 16
#define HDIM 64
#define WIN 8
#define PH 256
#define BH (BSZ*NH)
#define NROWS (SEQ*BSZ)
#define PROWS (PH*BSZ)

// -------- scratch (device globals) --------
__device__ float g_qbf[BH*SEQ*HDIM];   // Q base, A-frag per head
__device__ float g_kbf[BH*SEQ*HDIM];   // K base, B-frag per head
__device__ float g_v  [BH*SEQ*HDIM];   // V row-major head layout (for gv)
__device__ float g_vtf[BH*SEQ*HDIM];   // V transposed B-frag (sigma on key)
__device__ float g_qgf[BH*SEQ*HDIM];   // Q gauss, A-frag
__device__ float g_kgf[BH*PH*HDIM];    // K gauss, B-frag
__device__ float g_gvtf[BH*PH*HDIM];   // gauss-V, transposed B-frag (sigma)
__device__ float g_aof[NROWS*DIM];     // attention out, A-frag
__device__ float g_xsw [NROWS*DIM];
__device__ float g_phsw[PROWS*DIM];
__device__ float g_wsw [6*DIM*DIM];

// ================= helpers =================
__device__ __forceinline__ uint32_t f2tf(float x){
    uint32_t r; asm("cvt.rna.tf32.f32 %0, %1;" : "=r"(r) : "f"(x)); return r;
}
__device__ __forceinline__ float tf(float x){ return __uint_as_float(f2tf(x)); }
__device__ __forceinline__ void mma_tf32_16n8k8(float* d, const uint32_t* a, const uint32_t* b){
    asm volatile(
        "mma.sync.aligned.m16n8k8.row.col.f32.tf32.tf32.f32 "
        "{%0,%1,%2,%3}, {%4,%5,%6,%7}, {%8,%9}, {%0,%1,%2,%3};"
        : "+f"(d[0]), "+f"(d[1]), "+f"(d[2]), "+f"(d[3])
        : "r"(a[0]), "r"(a[1]), "r"(a[2]), "r"(a[3]), "r"(b[0]), "r"(b[1]));
}
__device__ __forceinline__ uint32_t smem_u32(const void* p){
    uint32_t a;
    asm("{ .reg .u64 t; cvta.to.shared.u64 t, %1; cvt.u32.u64 %0, t; }" : "=r"(a) : "l"(p));
    return a;
}
__device__ __forceinline__ void cpa16(uint32_t sm, const void* g){
    asm volatile("cp.async.cg.shared.global [%0], [%1], 16;" :: "r"(sm), "l"(g));
}
__device__ __forceinline__ void cp_commit(){ asm volatile("cp.async.commit_group;"); }
template<int N> __device__ __forceinline__ void cp_wait(){ asm volatile("cp.async.wait_group %0;" :: "n"(N)); }

// ================= operand pre-swizzle =================
__global__ __launch_bounds__(256) void conv_A(const float* __restrict__ src,
                                              float* __restrict__ dst, int M)
{
    int idx = blockIdx.x*256 + threadIdx.x;
    int total = (M >> 4)*128*32;
    if (idx >= total) return;
    int lane = idx & 31;
    int kt = (idx >> 5) & 127;
    int mt = idx >> 12;
    int m = mt*16 + (lane >> 2);
    int k = kt*8 + (lane & 3);
    const float* s = src + (size_t)m*DIM + k;
    float4 o;
    o.x = tf(s[0]); o.y = tf(s[8*DIM]); o.z = tf(s[4]); o.w = tf(s[8*DIM + 4]);
    *(float4*)(dst + (size_t)idx*4) = o;
}

__global__ __launch_bounds__(256) void conv_W6(
    const float* __restrict__ w0, const float* __restrict__ w1,
    const float* __restrict__ w2, const float* __restrict__ w3,
    const float* __restrict__ w4, const float* __restrict__ w5,
    float* __restrict__ dst)
{
    int z = blockIdx.y;
    const float* s;
    switch (z){
        case 0: s = w0; break; case 1: s = w1; break; case 2: s = w2; break;
        case 3: s = w3; break; case 4: s = w4; break; default: s = w5; break;
    }
    int idx = blockIdx.x*256 + threadIdx.x;
    int lane = idx & 31;
    int kt = (idx >> 5) & 127;
    int nt = idx >> 12;
    int n = nt*8 + (lane >> 2);
    int k = kt*8 + (lane & 3);
    const float* p = s + (size_t)n*DIM + k;
    float2 o; o.x = tf(p[0]); o.y = tf(p[4]);
    *(float2*)(dst + (size_t)z*DIM*DIM + (size_t)idx*2) = o;
}

__global__ __launch_bounds__(256) void maxpool_swz(const float* __restrict__ q,
                                                   float* __restrict__ dst)
{
    int idx = blockIdx.x*256 + threadIdx.x;
    int total = (PROWS >> 4)*128*32;
    if (idx >= total) return;
    int lane = idx & 31;
    int kt = (idx >> 5) & 127;
    int mt = idx >> 12;
    int m = mt*16 + (lane >> 2);
    int k = kt*8 + (lane & 3);
    float4 o; float* op = (float*)&o;
    #pragma unroll
    for (int e = 0; e < 4; e++){
        int mm = m + 8*(e & 1);
        int kk = k + 4*(e >> 1);
        int p = mm >> 1, b = mm & 1;
        float v = -1e30f;
        #pragma unroll
        for (int w = 0; w < WIN; w++)
            v = fmaxf(v, q[((size_t)((p*WIN + w)*BSZ + b))*DIM + kk]);
        op[e] = tf(v);
    }
    *(float4*)(dst + (size_t)idx*4) = o;
}

// ================= cp.async pipelined tf32 GEMM =================
#define STAGES 3
#define SM_A 4096
#define SM_B 4096
#define STAGE_F (SM_A + SM_B)
#define GEMM_SMEM (STAGES*STAGE_F*4)

// mode: 0=row-major out, 1=A-frag out, 2=B-frag out, 3=V dual (row-major + vtf)
__device__ __forceinline__ void gemm_body(
    const float* __restrict__ Asw, const float* __restrict__ Bsw,
    const float* __restrict__ bias, float* __restrict__ out, float* __restrict__ out2,
    float scale, int mode, int lenSeq, float* sm)
{
    int t = threadIdx.x, lane = t & 31, wid = t >> 5;
    int m0 = blockIdx.y*128, n0 = blockIdx.x*128;
    int my0 = blockIdx.y*8,  ny0 = blockIdx.x*16;
    uint32_t smb = smem_u32(sm);

    #define ISSUE(c, s) do { \
        uint32_t sa_ = smb + (uint32_t)((s)*STAGE_F)*4; \
        uint32_t sb_ = sa_ + SM_A*4; \
        _Pragma("unroll") \
        for (int i = 0; i < 4; i++){ \
            int lin = t + i*256; \
            int ab = lin >> 5, aoff = lin & 31; \
            const float* ga = Asw + (((size_t)(my0 + (ab >> 2))*128 + (c)*4 + (ab & 3))*128 + aoff*4); \
            cpa16(sa_ + (uint32_t)lin*16, ga); \
            int bb = lin >> 4, boff = lin & 15; \
            const float* gb = Bsw + (((size_t)(ny0 + (bb >> 2))*128 + (c)*4 + (bb & 3))*64 + boff*4); \
            cpa16(sb_ + (uint32_t)lin*16, gb); \
        } \
        cp_commit(); \
    } while(0)

    ISSUE(0, 0);
    ISSUE(1, 1);

    float acc[4][4][4] = {};
    int mtw0 = (wid & 1)*4, ntw0 = (wid >> 1)*4;

    #pragma unroll 1
    for (int c = 0; c < 32; c++){
        cp_wait<STAGES-2>();
        __syncthreads();
        if (c + 2 < 32){ int s2 = (c + 2) % STAGES; ISSUE(c+2, s2); }
        const float* sa = sm + (c % STAGES)*STAGE_F;
        const float* sbp = sa + SM_A;
        #pragma unroll
        for (int ks = 0; ks < 4; ks++){
            uint32_t af[4][4], bf[4][2];
            #pragma unroll
            for (int mt = 0; mt < 4; mt++){
                float4 v = *(const float4*)(sa + ((mtw0 + mt)*4 + ks)*128 + lane*4);
                af[mt][0]=__float_as_uint(v.x); af[mt][1]=__float_as_uint(v.y);
                af[mt][2]=__float_as_uint(v.z); af[mt][3]=__float_as_uint(v.w);
            }
            #pragma unroll
            for (int nt = 0; nt < 4; nt++){
                float2 v = *(const float2*)(sbp + ((ntw0 + nt)*4 + ks)*64 + lane*2);
                bf[nt][0]=__float_as_uint(v.x); bf[nt][1]=__float_as_uint(v.y);
            }
            #pragma unroll
            for (int mt = 0; mt < 4; mt++)
                #pragma unroll
                for (int nt = 0; nt < 4; nt++)
                    mma_tf32_16n8k8(acc[mt][nt], af[mt], bf[nt]);
        }
    }
    #undef ISSUE

    int r = lane >> 2, q = lane & 3;
    #pragma unroll
    for (int mt = 0; mt < 4; mt++){
        #pragma unroll
        for (int half = 0; half < 2; half++){
            int rr = m0 + (wid & 1)*64 + mt*16 + r + half*8;
            #pragma unroll
            for (int nt = 0; nt < 4; nt++){
                int cc0 = n0 + (wid >> 1)*32 + nt*8 + 2*q;
                float v0 = (acc[mt][nt][half*2+0] + bias[cc0])   * scale;
                float v1 = (acc[mt][nt][half*2+1] + bias[cc0+1]) * scale;
                if (mode == 0){
                    float* op = out + (size_t)rr*DIM + cc0;
                    op[0] = v0; op[1] = v1;
                } else {
                    int s = rr >> 1, bb = rr & 1;
                    int head = bb*NH + (cc0 >> 6);
                    size_t hb = (size_t)head*lenSeq*HDIM;
                    #pragma unroll
                    for (int e4 = 0; e4 < 2; e4++){
                        int cc = cc0 + e4;
                        int hd = cc & 63;
                        float v = e4 ? v1 : v0;
                        if (mode == 1){
                            int off = ((s >> 4)*8 + (hd >> 3))*128 + ((s & 7)*4 + (hd & 3))*4
                                    + ((s >> 3) & 1) + 2*((hd >> 2) & 1);
                            out[hb + off] = tf(v);     // RNA round for mma consumption
                        } else if (mode == 2){
                            int off = (s >> 6)*4096 + (((s >> 3) & 7)*8 + (hd >> 3))*64
                                    + ((s & 7)*4 + (hd & 3))*2 + ((hd >> 2) & 1);
                            out[hb + off] = tf(v);     // RNA round
                        } else {
                            out[hb + (size_t)s*HDIM + hd] = v;        // row-major V, full fp32 (feeds gv)
                            int c7 = s & 7;
                            int kst = ((c7 & 1) << 2) | (c7 >> 1);    // sigma
                            int off = (s >> 6)*4096 + ((hd >> 3)*8 + ((s >> 3) & 7))*64
                                    + ((hd & 7)*4 + (kst & 3))*2 + ((kst >> 2) & 1);
                            out2[hb + off] = tf(v);    // RNA round
                        }
                    }
                }
            }
        }
    }
}

// merged projections: z: 0=qb(A-frag,.125) 1=kb(B-frag) 2=v(dual) 3=qg(A-frag,.125) 4=kg(B-frag, PH)
__global__ __launch_bounds__(256, 2) void mm_proj(
    const float* __restrict__ xsw, const float* __restrict__ phsw,
    const float* __restrict__ wsw,
    const float* b0, const float* b1, const float* b2, const float* b3, const float* b4,
    float* o0, float* o1, float* o2, float* o2b, float* o3, float* o4)
{
    extern __shared__ float sm[];
    int z = blockIdx.z;
    if (z == 4 && blockIdx.y >= PROWS/128) return;
    const float* A = (z == 4) ? phsw : xsw;
    float* O; float* O2 = 0; const float* bias; int mode; float sc = 1.f; int lenSeq = SEQ;
    switch (z){
        case 0: bias = b0; O = o0; mode = 1; sc = 0.125f; break;
        case 1: bias = b1; O = o1; mode = 2; break;
        case 2: bias = b2; O = o2; O2 = o2b; mode = 3; break;
        case 3: bias = b3; O = o3; mode = 1; sc = 0.125f; break;
        default: bias = b4; O = o4; mode = 2; lenSeq = PH; break;
    }
    const float* B = wsw + (size_t)z*DIM*DIM;
    gemm_body(A, B, bias, O, O2, sc, mode, lenSeq, sm);
}

__global__ __launch_bounds__(256, 2) void mm_swz(
    const float* __restrict__ Asw, const float* __restrict__ Bsw,
    const float* __restrict__ bias, float* __restrict__ out)
{
    extern __shared__ float sm[];
    gemm_body(Asw, Bsw, bias, out, 0, 1.f, 0, SEQ, sm);
}

// ================= gv -> transposed B-frag (sigma baked) =================
__global__ __launch_bounds__(64) void gv_kernel()
{
    int p = blockIdx.x, head = blockIdx.y, hd = threadIdx.x;
    float mu = p*WIN + (WIN-1)*0.5f;
    int j0 = p*WIN - 28; if (j0 < 0) j0 = 0;
    int j1 = p*WIN + 36; if (j1 > SEQ) j1 = SEQ;
    const float coef = 0.19947114020071635f;
    const float* vp = g_v + (size_t)head*SEQ*HDIM;
    float acc = 0.f;
    for (int j = j0; j < j1; j++) {
        float d = (float)j - mu;
        float w = coef * __expf(-d*d*0.125f);
        acc = fmaf(w, vp[(size_t)j*HDIM + hd], acc);
    }
    int c7 = p & 7;
    int kst = ((c7 & 1) << 2) | (c7 >> 1);
    int off = (p >> 6)*4096 + ((hd >> 3)*8 + ((p >> 3) & 7))*64
            + ((hd & 7)*4 + (kst & 3))*2 + ((kst >> 2) & 1);
    g_gvtf[(size_t)head*PH*HDIM + off] = tf(acc);
}

// ================= tf32 mma flash attention, frag-native + cp.async =================
#define PST 68
#define TILE_F 4096
#define ATT_SMEM ((4*TILE_F + 4*16*PST)*4)   // 82944 B

__device__ __forceinline__ void attn_branch2(
    const float* __restrict__ Kf, const float* __restrict__ Vf, int ntiles,
    const uint32_t (&qf)[8][4], float (&O)[8][4], float& l0, float& l1,
    float* __restrict__ sK, float* __restrict__ sV, float* __restrict__ Pw, int t)
{
    int lane = t & 31, r = lane >> 2, q = lane & 3;
    uint32_t kb0 = smem_u32(sK), vb0 = smem_u32(sV);
    float mr0 = -1e30f, mr1 = -1e30f;
    l0 = 0.f; l1 = 0.f;

    // prefetch tile 0 into buf 0
    #pragma unroll
    for (int i = 0; i < 8; i++){
        int id = t + i*128;
        cpa16(kb0 + (uint32_t)id*16, Kf + (size_t)id*4);
        cpa16(vb0 + (uint32_t)id*16, Vf + (size_t)id*4);
    }
    cp_commit();

    #pragma unroll 1
    for (int tile = 0; tile < ntiles; tile++){
        int buf = tile & 1;
        if (tile + 1 < ntiles){
            uint32_t ka = kb0 + (uint32_t)((tile+1)&1)*16384u;
            uint32_t va = vb0 + (uint32_t)((tile+1)&1)*16384u;
            const float* Kg = Kf + (size_t)(tile+1)*TILE_F;
            const float* Vg = Vf + (size_t)(tile+1)*TILE_F;
            #pragma unroll
            for (int i = 0; i < 8; i++){
                int id = t + i*128;
                cpa16(ka + (uint32_t)id*16, Kg + (size_t)id*4);
                cpa16(va + (uint32_t)id*16, Vg + (size_t)id*4);
            }
            cp_commit();
            cp_wait<1>();
        } else {
            cp_wait<0>();
        }
        __syncthreads();

        const float* kb = sK + buf*TILE_F;
        const float* vb = sV + buf*TILE_F;

        // ---- scores ----
        float s[8][4] = {};
        #pragma unroll
        for (int ks = 0; ks < 8; ks++){
            #pragma unroll
            for (int nt = 0; nt < 8; nt++){
                float2 b = *(const float2*)(kb + (nt*8 + ks)*64 + lane*2);
                uint32_t bf[2] = {__float_as_uint(b.x), __float_as_uint(b.y)};
                mma_tf32_16n8k8(s[nt], qf[ks], bf);
            }
        }

        // ---- online softmax ----
        float tm0 = -1e30f, tm1 = -1e30f;
        #pragma unroll
        for (int nt = 0; nt < 8; nt++){
            tm0 = fmaxf(tm0, fmaxf(s[nt][0], s[nt][1]));
            tm1 = fmaxf(tm1, fmaxf(s[nt][2], s[nt][3]));
        }
        tm0 = fmaxf(tm0, __shfl_xor_sync(0xffffffffu, tm0, 1));
        tm0 = fmaxf(tm0, __shfl_xor_sync(0xffffffffu, tm0, 2));
        tm1 = fmaxf(tm1, __shfl_xor_sync(0xffffffffu, tm1, 1));
        tm1 = fmaxf(tm1, __shfl_xor_sync(0xffffffffu, tm1, 2));
        float mn0 = fmaxf(mr0, tm0), mn1 = fmaxf(mr1, tm1);
        float c0 = __expf(mr0 - mn0), c1 = __expf(mr1 - mn1);
        mr0 = mn0; mr1 = mn1;
        float ps0 = 0.f, ps1 = 0.f;
        #pragma unroll
        for (int nt = 0; nt < 8; nt++){
            float p00 = __expf(s[nt][0] - mn0), p01 = __expf(s[nt][1] - mn0);
            float p10 = __expf(s[nt][2] - mn1), p11 = __expf(s[nt][3] - mn1);
            ps0 += p00 + p01; ps1 += p10 + p11;
            Pw[r*PST + nt*8 + q]           = tf(p00);
            Pw[r*PST + nt*8 + q + 4]       = tf(p01);
            Pw[(r+8)*PST + nt*8 + q]       = tf(p10);
            Pw[(r+8)*PST + nt*8 + q + 4]   = tf(p11);
        }
        ps0 += __shfl_xor_sync(0xffffffffu, ps0, 1);
        ps0 += __shfl_xor_sync(0xffffffffu, ps0, 2);
        ps1 += __shfl_xor_sync(0xffffffffu, ps1, 1);
        ps1 += __shfl_xor_sync(0xffffffffu, ps1, 2);
        l0 = l0*c0 + ps0; l1 = l1*c1 + ps1;
        #pragma unroll
        for (int nt = 0; nt < 8; nt++){
            O[nt][0] *= c0; O[nt][1] *= c0; O[nt][2] *= c1; O[nt][3] *= c1;
        }
        __syncwarp();

        // ---- PV ----
        #pragma unroll
        for (int ks = 0; ks < 8; ks++){
            uint32_t af[4];
            const float* pp = Pw + r*PST + ks*8 + q;
            af[0] = __float_as_uint(pp[0]);
            af[1] = __float_as_uint(pp[8*PST]);
            af[2] = __float_as_uint(pp[4]);
            af[3] = __float_as_uint(pp[8*PST + 4]);
            #pragma unroll
            for (int nt = 0; nt < 8; nt++){
                float2 b = *(const float2*)(vb + (nt*8 + ks)*64 + lane*2);
                uint32_t bf2[2] = {__float_as_uint(b.x), __float_as_uint(b.y)};
                mma_tf32_16n8k8(O[nt], af, bf2);
            }
        }
        __syncthreads();
    }
}

__global__ __launch_bounds__(128) void attn_tc()
{
    extern __shared__ float smf[];
    float* sK = smf;                  // 2 bufs x 4096
    float* sV = smf + 2*TILE_F;       // 2 bufs x 4096
    float* Ps = smf + 4*TILE_F;

    int t = threadIdx.x, lane = t & 31, wid = t >> 5;
    int head = blockIdx.y, m0 = blockIdx.x*64;
    int r = lane >> 2, q = lane & 3;
    float* Pw = Ps + wid*16*PST;

    // Q base fragments: direct LDG.128
    uint32_t qf[8][4];
    const float* qp = g_qbf + (size_t)head*SEQ*HDIM + (size_t)((m0 >> 4) + wid)*1024;
    #pragma unroll
    for (int ks = 0; ks < 8; ks++)
        *(uint4*)qf[ks] = *(const uint4*)(qp + ks*128 + lane*4);

    float Of[8][4];
    {
        float O[8][4] = {}; float l0, l1;
        attn_branch2(g_kbf + (size_t)head*SEQ*HDIM, g_vtf + (size_t)head*SEQ*HDIM,
                     SEQ/64, qf, O, l0, l1, sK, sV, Pw, t);
        float i0 = 0.5f/l0, i1 = 0.5f/l1;
        #pragma unroll
        for (int nt = 0; nt < 8; nt++){
            Of[nt][0] = O[nt][0]*i0; Of[nt][1] = O[nt][1]*i0;
            Of[nt][2] = O[nt][2]*i1; Of[nt][3] = O[nt][3]*i1;
        }
    }

    // Q gauss fragments
    const float* qgp = g_qgf + (size_t)head*SEQ*HDIM + (size_t)((m0 >> 4) + wid)*1024;
    #pragma unroll
    for (int ks = 0; ks < 8; ks++)
        *(uint4*)qf[ks] = *(const uint4*)(qgp + ks*128 + lane*4);
    {
        float O[8][4] = {}; float l0, l1;
        attn_branch2(g_kgf + (size_t)head*PH*HDIM, g_gvtf + (size_t)head*PH*HDIM,
                     PH/64, qf, O, l0, l1, sK, sV, Pw, t);
        float i0 = 0.5f/l0, i1 = 0.5f/l1;
        #pragma unroll
        for (int nt = 0; nt < 8; nt++){
            Of[nt][0] += O[nt][0]*i0; Of[nt][1] += O[nt][1]*i0;
            Of[nt][2] += O[nt][2]*i1; Of[nt][3] += O[nt][3]*i1;
        }
    }

    // epilogue: write A-frag layout over (m = s*BSZ+b, k = h*64+d)
    int b = head / NH, h = head % NH;
    int s0 = m0 + wid*16 + r;
    #pragma unroll
    for (int nt = 0; nt < 8; nt++){
        int cc = h*64 + nt*8 + 2*q;
        #pragma unroll
        for (int vi = 0; vi < 4; vi++){
            int srow = s0 + ((vi >= 2) ? 8 : 0);
            int k = cc + (vi & 1);
            int m = srow*2 + b;
            int off = (m >> 4)*16384 + (k >> 3)*128 + ((m & 7)*4 + (k & 3))*4
                    + ((m >> 3) & 1) + 2*((k >> 2) & 1);
            g_aof[off] = tf(Of[nt][vi]);
        }
    }
}

// ================= launch =================
extern "C" void kernel_launch(void* const* d_in, const int* in_sizes, int n_in,
                              void* d_out, int out_size)
{
    const float* query = (const float*)d_in[0];
    const float* Wqb = (const float*)d_in[1];  const float* bqb = (const float*)d_in[2];
    const float* Wkb = (const float*)d_in[3];  const float* bkb = (const float*)d_in[4];
    const float* Wqg = (const float*)d_in[5];  const float* bqg = (const float*)d_in[6];
    const float* Wkg = (const float*)d_in[7];  const float* bkg = (const float*)d_in[8];
    const float* Wv  = (const float*)d_in[9];  const float* bv  = (const float*)d_in[10];
    const float* Wo  = (const float*)d_in[11]; const float* bo  = (const float*)d_in[12];
    float* out = (float*)d_out;

    float *p_qbf, *p_kbf, *p_v, *p_vtf, *p_qgf, *p_kgf, *p_aof;
    float *p_xsw, *p_phsw, *p_wsw;
    cudaGetSymbolAddress((void**)&p_qbf, g_qbf);
    cudaGetSymbolAddress((void**)&p_kbf, g_kbf);
    cudaGetSymbolAddress((void**)&p_v,   g_v);
    cudaGetSymbolAddress((void**)&p_vtf, g_vtf);
    cudaGetSymbolAddress((void**)&p_qgf, g_qgf);
    cudaGetSymbolAddress((void**)&p_kgf, g_kgf);
    cudaGetSymbolAddress((void**)&p_aof, g_aof);
    cudaGetSymbolAddress((void**)&p_xsw,  g_xsw);
    cudaGetSymbolAddress((void**)&p_phsw, g_phsw);
    cudaGetSymbolAddress((void**)&p_wsw,  g_wsw);

    cudaFuncSetAttribute(mm_proj, cudaFuncAttributeMaxDynamicSharedMemorySize, GEMM_SMEM);
    cudaFuncSetAttribute(mm_swz,  cudaFuncAttributeMaxDynamicSharedMemorySize, GEMM_SMEM);
    cudaFuncSetAttribute(attn_tc, cudaFuncAttributeMaxDynamicSharedMemorySize, ATT_SMEM);

    conv_W6<<<dim3(2048, 6), 256>>>(Wqb, Wkb, Wv, Wqg, Wkg, Wo, p_wsw);
    conv_A<<<4096, 256>>>(query, p_xsw, NROWS);
    maxpool_swz<<<512, 256>>>(query, p_phsw);

    mm_proj<<<dim3(DIM/128, NROWS/128, 5), 256, GEMM_SMEM>>>(
        p_xsw, p_phsw, p_wsw,
        bqb, bkb, bv, bqg, bkg,
        p_qbf, p_kbf, p_v, p_vtf, p_qgf, p_kgf);

    gv_kernel<<<dim3(PH, BH), HDIM>>>();

    attn_tc<<<dim3(SEQ/64, BH), 128, ATT_SMEM>>>();

    mm_swz<<<dim3(DIM/128, NROWS/128), 256, GEMM_SMEM>>>(p_aof, p_wsw + (size_t)5*DIM*DIM, bo, out);
}